// round 11
// baseline (speedup 1.0000x reference)
#include <cuda_runtime.h>
#include <cuda_bf16.h>
#include <math.h>
#include <stdint.h>

#define NT   768
#define HD   64
#define FD   32
#define LL   2
#define OUTD 64
#define VEC_OUT (NT * 6)
#define INV_T1 (1.0f / 767.0f)

typedef unsigned long long ull;

// ---------------- device scratch ----------------
__device__ float  g_h[NT * HD];
__device__ float  g_x8[NT * 8];
__device__ float  g_A[NT * HD];     // plain per-channel layout
__device__ float  g_B[NT * HD];     // plain (incl be1)
__device__ float  g_agg[NT * HD];
__device__ float  g_xupd[NT * 6];

__device__ __forceinline__ float silu(float x) {
    float t;
    asm("tanh.approx.f32 %0, %1;" : "=f"(t) : "f"(0.5f * x));
    return x * fmaf(0.5f, t, 0.5f);
}
__device__ __forceinline__ uint32_t smem_u32(const void* p) {
    uint32_t a;
    asm("{ .reg .u64 t; cvta.to.shared.u64 t, %1; cvt.u32.u64 %0, t; }"
        : "=r"(a) : "l"(p));
    return a;
}
__device__ __forceinline__ uint32_t sw128(uint32_t off) {
    return off ^ ((off >> 3) & 0x70);
}

#define LDSM4(r, a) \
    asm volatile("ldmatrix.sync.aligned.m8n8.x4.shared.b16 {%0,%1,%2,%3}, [%4];" \
        : "=r"((r)[0]), "=r"((r)[1]), "=r"((r)[2]), "=r"((r)[3]) : "r"(a))

#define MMA16(d, a, b0, b1) \
    asm volatile("mma.sync.aligned.m16n8k16.row.col.f32.bf16.bf16.f32 " \
        "{%0,%1,%2,%3},{%4,%5,%6,%7},{%8,%9},{%0,%1,%2,%3};" \
        : "+f"((d)[0]), "+f"((d)[1]), "+f"((d)[2]), "+f"((d)[3]) \
        : "r"((a)[0]), "r"((a)[1]), "r"((a)[2]), "r"((a)[3]), "r"(b0), "r"(b1))

// ---------------- smem layout ----------------
#define S_AHI 0
#define S_ALO 16384
#define S_W2H 32768
#define S_W2L 40960
#define S_WXH 49152
#define S_WXL 57344
#define S_AUX 65536
#define AX_WQ    0        // float2[64]  512
#define AX_BR    512      // float[64]   256
#define AX_BE2   768      // float[64]   256
#define AX_BX1   1024     // float[64]   256
#define AX_WX2   1280     // float2[64]  512
#define AX_WPART 1792     // float[8*64] 2048
#define AX_SPHI  3840     // float[256]  1024
#define AX_SXU   4864     // float[6]+pad
#define EDGE_SMEM (65536 + 4896)

// GEMM (m16 warp-tile), A from smem hi/lo tiles
__device__ __forceinline__ void gemm_smemA16(uint32_t smb, uint32_t wOff,
                                             int warp, int lane, float acc[8][4]) {
    const int rowA = 16 * warp + (lane & 15);
    const uint32_t selA = ((uint32_t)lane >> 4) << 4;
    const uint32_t aBase = smb + S_AHI + rowA * 128;
    const uint32_t mA = (rowA & 7) << 4;
    const int rowB = (lane & 7) + ((lane & 16) >> 1);
    const uint32_t selB = ((uint32_t)lane & 8) << 1;
    const uint32_t bBase = smb + wOff + rowB * 128;
    const uint32_t mB = (rowB & 7) << 4;
#pragma unroll
    for (int kt = 0; kt < 4; kt++) {
        uint32_t aAddr = aBase + ((32u * kt + selA) ^ mA);
        uint32_t ah[4], al[4];
        LDSM4(ah, aAddr);
        LDSM4(al, aAddr + 16384);
        uint32_t bx = (32u * kt + selB) ^ mB;
#pragma unroll
        for (int np = 0; np < 4; np++) {
            uint32_t bAddr = bBase + np * 2048 + bx;
            uint32_t bh[4], bl[4];
            LDSM4(bh, bAddr);
            LDSM4(bl, bAddr + 8192);
            MMA16(acc[2 * np], ah, bh[0], bh[1]);
            MMA16(acc[2 * np], ah, bl[0], bl[1]);
            MMA16(acc[2 * np], al, bh[0], bh[1]);
            MMA16(acc[2 * np + 1], ah, bh[2], bh[3]);
            MMA16(acc[2 * np + 1], ah, bl[2], bl[3]);
            MMA16(acc[2 * np + 1], al, bh[2], bh[3]);
        }
    }
}

// GEMM (m16), A fragments in registers
__device__ __forceinline__ void gemm_regA16(uint32_t smb, uint32_t wOff, int lane,
                                            const uint32_t mhi[16],
                                            const uint32_t mlo[16],
                                            float acc[8][4]) {
    const int rowB = (lane & 7) + ((lane & 16) >> 1);
    const uint32_t selB = ((uint32_t)lane & 8) << 1;
    const uint32_t bBase = smb + wOff + rowB * 128;
    const uint32_t mB = (rowB & 7) << 4;
#pragma unroll
    for (int kt = 0; kt < 4; kt++) {
        uint32_t bx = (32u * kt + selB) ^ mB;
        const uint32_t* ah = &mhi[4 * kt];
        const uint32_t* al = &mlo[4 * kt];
#pragma unroll
        for (int np = 0; np < 4; np++) {
            uint32_t bAddr = bBase + np * 2048 + bx;
            uint32_t bh[4], bl[4];
            LDSM4(bh, bAddr);
            LDSM4(bl, bAddr + 8192);
            MMA16(acc[2 * np], ah, bh[0], bh[1]);
            MMA16(acc[2 * np], ah, bl[0], bl[1]);
            MMA16(acc[2 * np], al, bh[0], bh[1]);
            MMA16(acc[2 * np + 1], ah, bh[2], bh[3]);
            MMA16(acc[2 * np + 1], ah, bl[2], bl[3]);
            MMA16(acc[2 * np + 1], al, bh[2], bh[3]);
        }
    }
}

// ---------------- init ----------------
__global__ void k_init(const float* __restrict__ feat,
                       const float* __restrict__ w_emb,
                       const float* __restrict__ b_emb,
                       const float* __restrict__ pos,
                       const float* __restrict__ we1,
                       const float* __restrict__ be1) {
    __shared__ float fs[4][FD], hs[4][HD];
    int g = threadIdx.x >> 6, j = threadIdx.x & 63;
    int t = blockIdx.x * 4 + g;
    if (j < FD) fs[g][j] = feat[t * FD + j];
    __syncthreads();
    float acc = b_emb[j];
#pragma unroll
    for (int i = 0; i < FD; i++) acc += fs[g][i] * w_emb[i * HD + j];
    g_h[t * HD + j] = acc;
    hs[g][j] = acc;
    if (j < 8) g_x8[t * 8 + j] = (j < 6) ? pos[t * 3 + (j % 3)] : 0.0f;
    __syncthreads();
    if (j < 32) {
        const float* w = we1;
        float alo = 0, ahi = 0;
        float blo = be1[j], bhi = be1[j + 32];
#pragma unroll 8
        for (int i = 0; i < HD; i++) {
            float hv = hs[g][i];
            alo += hv * w[i * HD + j];
            ahi += hv * w[i * HD + j + 32];
            blo += hv * w[(64 + i) * HD + j];
            bhi += hv * w[(64 + i) * HD + j + 32];
        }
        g_A[t * 64 + j] = alo;  g_A[t * 64 + j + 32] = ahi;
        g_B[t * 64 + j] = blo;  g_B[t * 64 + j + 32] = bhi;
    }
}

// ---------------- mma.sync edge kernel: 256 thr / receiver, m16 warp tiles -
__global__ void __launch_bounds__(256, 2)
k_edge_mma(const float* __restrict__ we1, const float* __restrict__ we2,
           const float* __restrict__ be2, const float* __restrict__ wx1,
           const float* __restrict__ bx1, const float* __restrict__ wx2,
           int layer) {
    const float* we1l = we1 + layer * 130 * HD;
    const float* we2l = we2 + layer * HD * HD;
    const float* wx1l = wx1 + layer * HD * HD;
    const float* wx2l = wx2 + layer * HD * 2;
    const float* be2l = be2 + layer * HD;
    const float* bx1l = bx1 + layer * HD;

    extern __shared__ char sm[];
    char* aux = sm + S_AUX;
    float2* swqA = (float2*)(aux + AX_WQ);
    float*  sbrA = (float*)(aux + AX_BR);
    float*  sbe2 = (float*)(aux + AX_BE2);
    float*  sbx1 = (float*)(aux + AX_BX1);
    float2* swx2 = (float2*)(aux + AX_WX2);
    float*  wpart = (float*)(aux + AX_WPART);
    float*  sphi = (float*)(aux + AX_SPHI);
    float*  sxu  = (float*)(aux + AX_SXU);

    const int r = blockIdx.x;
    const int tid = threadIdx.x;
    const int warp = tid >> 5, lane = tid & 31;
    const int tig = lane & 3, gid = lane >> 2;
    const int e = tid & 127, hh = tid >> 7;     // 2 threads per edge row
    const uint32_t smb = smem_u32(sm);

    // ---- preload weights as W^T[n][k] bf16 hi/lo, SW128 rows ----
    {
        int n = tid & 63, kh = (tid >> 6) & 1;
        const float* wsrc = (tid < 128) ? we2l : wx1l;
        char* dH = sm + ((tid < 128) ? S_W2H : S_WXH);
        char* dL = dH + 8192;
        float wv[32];
#pragma unroll 8
        for (int kk = 0; kk < 32; kk++) wv[kk] = wsrc[(32 * kh + kk) * 64 + n];
#pragma unroll
        for (int jj = 0; jj < 4; jj++) {
            uint32_t hp[4], lp[4];
#pragma unroll
            for (int q = 0; q < 4; q++) {
                float t0 = wv[8 * jj + 2 * q], t1 = wv[8 * jj + 2 * q + 1];
                uint32_t hi;
                asm("cvt.rn.satfinite.bf16x2.f32 %0, %1, %2;" : "=r"(hi) : "f"(t1), "f"(t0));
                float f0 = t0 - __uint_as_float(hi << 16);
                float f1 = t1 - __uint_as_float(hi & 0xffff0000u);
                uint32_t lo;
                asm("cvt.rn.satfinite.bf16x2.f32 %0, %1, %2;" : "=r"(lo) : "f"(f1), "f"(f0));
                hp[q] = hi; lp[q] = lo;
            }
            uint32_t sw = sw128((uint32_t)(n * 128 + kh * 64 + jj * 16));
            *(uint4*)(dH + sw) = make_uint4(hp[0], hp[1], hp[2], hp[3]);
            *(uint4*)(dL + sw) = make_uint4(lp[0], lp[1], lp[2], lp[3]);
        }
    }
    if (tid < 64) {
        swqA[tid] = make_float2(we1l[8192 + tid], we1l[8256 + tid]);
        sbrA[tid] = g_B[r * 64 + tid];
        sbe2[tid] = be2l[tid];
        sbx1[tid] = bx1l[tid];
        swx2[tid] = make_float2(wx2l[2 * tid], wx2l[2 * tid + 1]);
    }
    if (tid < 6) sxu[tid] = 0.0f;
    __syncthreads();

    const float4 xra = *(const float4*)&g_x8[r * 8];
    const float4 xrb = *(const float4*)&g_x8[r * 8 + 4];

    float aggv[16];
#pragma unroll
    for (int i = 0; i < 16; i++) aggv[i] = 0.0f;
    float xacc[3] = {0, 0, 0};

    for (int tile = 0; tile < 6; tile++) {
        const int s0 = tile * 128;
        const int s = s0 + e;

        // ---- edge geometry ----
        float4 xa = __ldg((const float4*)&g_x8[s * 8]);
        float4 xb = __ldg((const float4*)&g_x8[s * 8 + 4]);
        float d0 = xa.x - xra.x, d1 = xa.y - xra.y, d2 = xa.z - xra.z;
        float d3 = xa.w - xra.w, d4 = xb.x - xrb.x, d5 = xb.y - xrb.y;
        float sq0 = d0 * d0 + d1 * d1 + d2 * d2;
        float sq1 = d3 * d3 + d4 * d4 + d5 * d5;
        float sdx, sdy, sdz;
        if (hh == 0) {
            float r0 = __fdividef(1.0f, __fsqrt_rn(sq0 + 1e-8f) + 1.0f);
            sdx = d0 * r0; sdy = d1 * r0; sdz = d2 * r0;
        } else {
            float r1 = __fdividef(1.0f, __fsqrt_rn(sq1 + 1e-8f) + 1.0f);
            sdx = d3 * r1; sdy = d4 * r1; sdz = d5 * r1;
        }

        // ---- t-fill: thread owns 32 channels of edge e ----
        {
            float tv[32];
            const float4* ap = (const float4*)&g_A[s * 64 + 32 * hh];
            const float2* wqp = swqA + 32 * hh;
            const float*  brp = sbrA + 32 * hh;
#pragma unroll
            for (int i4 = 0; i4 < 8; i4++) {
                float4 a4 = __ldg(&ap[i4]);
                float2 w0 = wqp[4 * i4], w1 = wqp[4 * i4 + 1];
                float2 w2 = wqp[4 * i4 + 2], w3 = wqp[4 * i4 + 3];
                tv[4 * i4 + 0] = silu(a4.x + brp[4 * i4 + 0] + sq0 * w0.x + sq1 * w0.y);
                tv[4 * i4 + 1] = silu(a4.y + brp[4 * i4 + 1] + sq0 * w1.x + sq1 * w1.y);
                tv[4 * i4 + 2] = silu(a4.z + brp[4 * i4 + 2] + sq0 * w2.x + sq1 * w2.y);
                tv[4 * i4 + 3] = silu(a4.w + brp[4 * i4 + 3] + sq0 * w3.x + sq1 * w3.y);
            }
#pragma unroll
            for (int j = 0; j < 4; j++) {
                uint32_t hp[4], lp[4];
#pragma unroll
                for (int q = 0; q < 4; q++) {
                    float t0 = tv[8 * j + 2 * q], t1 = tv[8 * j + 2 * q + 1];
                    uint32_t hi;
                    asm("cvt.rn.satfinite.bf16x2.f32 %0, %1, %2;" : "=r"(hi) : "f"(t1), "f"(t0));
                    float f0 = t0 - __uint_as_float(hi << 16);
                    float f1 = t1 - __uint_as_float(hi & 0xffff0000u);
                    uint32_t lo;
                    asm("cvt.rn.satfinite.bf16x2.f32 %0, %1, %2;" : "=r"(lo) : "f"(f1), "f"(f0));
                    hp[q] = hi; lp[q] = lo;
                }
                uint32_t sw = sw128((uint32_t)(e * 128 + hh * 64 + j * 16));
                *(uint4*)(sm + S_AHI + sw) = make_uint4(hp[0], hp[1], hp[2], hp[3]);
                *(uint4*)(sm + S_ALO + sw) = make_uint4(lp[0], lp[1], lp[2], lp[3]);
            }
        }
        __syncthreads();

        // ---- GEMM 1: m_pre = t @ we2 + be2 ----
        float acc[8][4];
        {
            int n0 = 2 * tig;
#pragma unroll
            for (int nt = 0; nt < 8; nt++) {
                float2 b = *(const float2*)&sbe2[8 * nt + n0];
                acc[nt][0] = b.x; acc[nt][1] = b.y;
                acc[nt][2] = b.x; acc[nt][3] = b.y;
            }
        }
        gemm_smemA16(smb, S_W2H, warp, lane, acc);

        // ---- epilogue 1: m = silu(.)*mask ; agg ; A-fragments in regs ----
        uint32_t mhi[16], mlo[16];
        {
            int rA = 16 * warp + gid;
            float vA = (s0 + rA != r) ? 1.0f : 0.0f;
            float vB = (s0 + rA + 8 != r) ? 1.0f : 0.0f;
#pragma unroll
            for (int nt = 0; nt < 8; nt++) {
                float m0 = silu(acc[nt][0]) * vA;
                float m1 = silu(acc[nt][1]) * vA;
                float m2 = silu(acc[nt][2]) * vB;
                float m3 = silu(acc[nt][3]) * vB;
                aggv[2 * nt]     += m0 + m2;
                aggv[2 * nt + 1] += m1 + m3;
                uint32_t h0, h1, l0, l1;
                asm("cvt.rn.satfinite.bf16x2.f32 %0, %1, %2;" : "=r"(h0) : "f"(m1), "f"(m0));
                asm("cvt.rn.satfinite.bf16x2.f32 %0, %1, %2;" : "=r"(h1) : "f"(m3), "f"(m2));
                float f0 = m0 - __uint_as_float(h0 << 16);
                float f1 = m1 - __uint_as_float(h0 & 0xffff0000u);
                float f2 = m2 - __uint_as_float(h1 << 16);
                float f3 = m3 - __uint_as_float(h1 & 0xffff0000u);
                asm("cvt.rn.satfinite.bf16x2.f32 %0, %1, %2;" : "=r"(l0) : "f"(f1), "f"(f0));
                asm("cvt.rn.satfinite.bf16x2.f32 %0, %1, %2;" : "=r"(l1) : "f"(f3), "f"(f2));
                mhi[2 * nt]     = h0;
                mhi[2 * nt + 1] = h1;
                mlo[2 * nt]     = l0;
                mlo[2 * nt + 1] = l1;
            }
        }

        // ---- GEMM 2: p_pre = m @ wx1 + bx1 ----
        {
            int n0 = 2 * tig;
#pragma unroll
            for (int nt = 0; nt < 8; nt++) {
                float2 b = *(const float2*)&sbx1[8 * nt + n0];
                acc[nt][0] = b.x; acc[nt][1] = b.y;
                acc[nt][2] = b.x; acc[nt][3] = b.y;
            }
        }
        gemm_regA16(smb, S_WXH, lane, mhi, mlo, acc);

        // ---- epilogue 2: q = silu(p); phi = q @ wx2 (quad partial) ----
        {
            float ph[2][2] = {{0, 0}, {0, 0}};
#pragma unroll
            for (int nt = 0; nt < 8; nt++) {
                int n0 = 8 * nt + 2 * tig;
                float4 w = *(const float4*)&swx2[n0];
                float q0 = silu(acc[nt][0]);
                float q1 = silu(acc[nt][1]);
                float q2 = silu(acc[nt][2]);
                float q3 = silu(acc[nt][3]);
                ph[0][0] += q0 * w.x + q1 * w.z;
                ph[0][1] += q0 * w.y + q1 * w.w;
                ph[1][0] += q2 * w.x + q3 * w.z;
                ph[1][1] += q2 * w.y + q3 * w.w;
            }
#pragma unroll
            for (int k = 0; k < 2; k++) {
#pragma unroll
                for (int c = 0; c < 2; c++) {
                    ph[k][c] += __shfl_xor_sync(0xffffffffu, ph[k][c], 1);
                    ph[k][c] += __shfl_xor_sync(0xffffffffu, ph[k][c], 2);
                }
            }
            if (tig == 0) {
#pragma unroll
                for (int k = 0; k < 2; k++) {
                    int row = 16 * warp + 8 * k + gid;
                    sphi[row * 2]     = ph[k][0];
                    sphi[row * 2 + 1] = ph[k][1];
                }
            }
        }
        __syncthreads();
        {
            float p = sphi[e * 2 + hh];
            xacc[0] += p * sdx; xacc[1] += p * sdy; xacc[2] += p * sdz;
        }
    }

    // ---- reductions ----
#pragma unroll
    for (int i = 0; i < 16; i++) {
        aggv[i] += __shfl_xor_sync(0xffffffffu, aggv[i], 4);
        aggv[i] += __shfl_xor_sync(0xffffffffu, aggv[i], 8);
        aggv[i] += __shfl_xor_sync(0xffffffffu, aggv[i], 16);
    }
    if (lane < 4) {
#pragma unroll
        for (int nt = 0; nt < 8; nt++) {
            wpart[warp * 64 + 8 * nt + 2 * lane]     = aggv[2 * nt];
            wpart[warp * 64 + 8 * nt + 2 * lane + 1] = aggv[2 * nt + 1];
        }
    }
#pragma unroll
    for (int c = 0; c < 3; c++) {
        float v = xacc[c];
#pragma unroll
        for (int off = 16; off > 0; off >>= 1)
            v += __shfl_xor_sync(0xffffffffu, v, off);
        if (lane == 0) atomicAdd(&sxu[3 * hh + c], v);
    }
    __syncthreads();
    if (tid < 64) {
        float sum = 0.0f;
#pragma unroll
        for (int w = 0; w < 8; w++) sum += wpart[w * 64 + tid];
        g_agg[r * HD + tid] = sum;
    }
    if (tid < 6) g_xupd[r * 6 + tid] = sxu[tid];
}

// ---------------- node update (+ fused A/B precompute) ----------------
__global__ void k_update(const float* __restrict__ wh1,
                         const float* __restrict__ bh1,
                         const float* __restrict__ wh2,
                         const float* __restrict__ bh2,
                         const float* __restrict__ we1,
                         const float* __restrict__ be1,
                         int layer, int next_layer) {
    __shared__ float hs[4][HD], as[4][HD], us[4][HD];
    int g = threadIdx.x >> 6, j = threadIdx.x & 63;
    int t = blockIdx.x * 4 + g;
    const float* w1 = wh1 + layer * 128 * HD;
    const float* w2 = wh2 + layer * HD * HD;
    hs[g][j] = g_h[t * HD + j];
    as[g][j] = g_agg[t * HD + j];
    __syncthreads();
    float u = bh1[layer * HD + j];
#pragma unroll 8
    for (int i = 0; i < HD; i++) u += hs[g][i] * w1[i * HD + j];
#pragma unroll 8
    for (int i = 0; i < HD; i++) u += as[g][i] * w1[(64 + i) * HD + j];
    us[g][j] = silu(u);
    __syncthreads();
    float o = bh2[layer * HD + j];
#pragma unroll 8
    for (int i = 0; i < HD; i++) o += us[g][i] * w2[i * HD + j];
    float hn = hs[g][j] + o;
    g_h[t * HD + j] = hn;
    if (j < 6) g_x8[t * 8 + j] += g_xupd[t * 6 + j] * INV_T1;
    if (next_layer < LL) {
        hs[g][j] = hn;
        __syncthreads();
        const float* w = we1 + next_layer * 130 * HD;
        if (j < 32) {
            float alo = 0, ahi = 0;
            float blo = be1[next_layer * HD + j], bhi = be1[next_layer * HD + j + 32];
#pragma unroll 8
            for (int i = 0; i < HD; i++) {
                float hv = hs[g][i];
                alo += hv * w[i * HD + j];
                ahi += hv * w[i * HD + j + 32];
                blo += hv * w[(64 + i) * HD + j];
                bhi += hv * w[(64 + i) * HD + j + 32];
            }
            g_A[t * 64 + j] = alo;  g_A[t * 64 + j + 32] = ahi;
            g_B[t * 64 + j] = blo;  g_B[t * 64 + j + 32] = bhi;
        }
    }
}

// ---------------- final head ----------------
__global__ void k_final(const float* __restrict__ pos,
                        const float* __restrict__ w_head,
                        const float* __restrict__ b_head,
                        float* __restrict__ out) {
    __shared__ float hs[4][HD];
    int g = threadIdx.x >> 6, j = threadIdx.x & 63;
    int t = blockIdx.x * 4 + g;
    hs[g][j] = g_h[t * HD + j];
    __syncthreads();
    float o = b_head[j];
#pragma unroll 8
    for (int i = 0; i < HD; i++) o += hs[g][i] * w_head[i * OUTD + j];
    out[VEC_OUT + t * OUTD + j] = o;
    if (j < 6) out[t * 6 + j] = g_x8[t * 8 + j] - pos[t * 3 + (j % 3)];
}

// ---------------- launch ----------------
extern "C" void kernel_launch(void* const* d_in, const int* in_sizes, int n_in,
                              void* d_out, int out_size) {
    const float* positions = (const float*)d_in[0];
    const float* features  = (const float*)d_in[1];
    const float* w_emb     = (const float*)d_in[2];
    const float* b_emb     = (const float*)d_in[3];
    const float* we1       = (const float*)d_in[4];
    const float* be1       = (const float*)d_in[5];
    const float* we2       = (const float*)d_in[6];
    const float* be2       = (const float*)d_in[7];
    const float* wx1       = (const float*)d_in[8];
    const float* bx1       = (const float*)d_in[9];
    const float* wx2       = (const float*)d_in[10];
    const float* wh1       = (const float*)d_in[11];
    const float* bh1       = (const float*)d_in[12];
    const float* wh2       = (const float*)d_in[13];
    const float* bh2       = (const float*)d_in[14];
    const float* w_head    = (const float*)d_in[15];
    const float* b_head    = (const float*)d_in[16];
    float* out = (float*)d_out;

    cudaFuncSetAttribute(k_edge_mma, cudaFuncAttributeMaxDynamicSharedMemorySize,
                         EDGE_SMEM);

    k_init<<<NT / 4, 256>>>(features, w_emb, b_emb, positions, we1, be1);
    for (int l = 0; l < LL; l++) {
        k_edge_mma<<<NT, 256, EDGE_SMEM>>>(we1, we2, be2, wx1, bx1, wx2, l);
        k_update<<<NT / 4, 256>>>(wh1, bh1, wh2, bh2, we1, be1, l, l + 1);
    }
    k_final<<<NT / 4, 256>>>(positions, w_head, b_head, out);
}

// round 12
// speedup vs baseline: 1.2496x; 1.2496x over previous
#include <cuda_runtime.h>
#include <cuda_fp16.h>
#include <math.h>
#include <stdint.h>

#define NT   768
#define HD   64
#define FD   32
#define LL   2
#define OUTD 64
#define VEC_OUT (NT * 6)
#define INV_T1 (1.0f / 767.0f)

typedef unsigned long long ull;

// ---------------- device scratch ----------------
__device__ float  g_h[NT * HD];
__device__ float  g_x8[NT * 8];
__device__ float2 g_A2[NT * 32];
__device__ float2 g_B2[NT * 32];
__device__ float  g_agg[NT * HD];
__device__ float  g_xupd[NT * 6];

__device__ __forceinline__ float silu(float x) {
    float t;
    asm("tanh.approx.f32 %0, %1;" : "=f"(t) : "f"(0.5f * x));
    return x * fmaf(0.5f, t, 0.5f);
}
__device__ __forceinline__ uint32_t smem_u32(const void* p) {
    uint32_t a;
    asm("{ .reg .u64 t; cvta.to.shared.u64 t, %1; cvt.u32.u64 %0, t; }"
        : "=r"(a) : "l"(p));
    return a;
}
__device__ __forceinline__ uint32_t sw128(uint32_t off) {
    return off ^ ((off >> 3) & 0x70);
}
__device__ __forceinline__ uint32_t packh2(float lo, float hi) {
    __half2 h = __floats2half2_rn(lo, hi);   // low 16 bits = first arg
    return *reinterpret_cast<uint32_t*>(&h);
}

#define LDSM4(r, a) \
    asm volatile("ldmatrix.sync.aligned.m8n8.x4.shared.b16 {%0,%1,%2,%3}, [%4];" \
        : "=r"((r)[0]), "=r"((r)[1]), "=r"((r)[2]), "=r"((r)[3]) : "r"(a))

#define MMA16(d, a, b0, b1) \
    asm volatile("mma.sync.aligned.m16n8k16.row.col.f32.f16.f16.f32 " \
        "{%0,%1,%2,%3},{%4,%5,%6,%7},{%8,%9},{%0,%1,%2,%3};" \
        : "+f"((d)[0]), "+f"((d)[1]), "+f"((d)[2]), "+f"((d)[3]) \
        : "r"((a)[0]), "r"((a)[1]), "r"((a)[2]), "r"((a)[3]), "r"(b0), "r"(b1))

// ---------------- smem layout ----------------
#define S_A   0           // fp16 activation tile: 128 x 64 x 2B = 16KB
#define S_W2H 16384       // we2^T fp16 hi  8KB
#define S_W2L 24576       // we2^T fp16 lo  8KB
#define S_WXH 32768       // wx1^T fp16 hi  8KB
#define S_WXL 40960       // wx1^T fp16 lo  8KB
#define S_AUX 49152
#define AX_WQ    0        // float4[32]  512
#define AX_BR    512      // float2[32]  256
#define AX_BE2   768      // float[64]   256
#define AX_BX1   1024     // float[64]   256
#define AX_WX2   1280     // float2[64]  512
#define AX_WPART 1792     // float[4*64] 1024
#define AX_SPHI  2816     // float[256]  1024
#define AX_SXU   3840     // float[6]+pad
#define EDGE_SMEM (49152 + 3872)

// GEMM: [128 x 64] fp16 A (smem) @ [64 x 64] (fp16 hi/lo weights), 2-pass
__device__ __forceinline__ void gemm_smemA(uint32_t smb, uint32_t wOff, int warp,
                                           int lane, float acc[2][8][4]) {
    const int rowA = 32 * warp + (lane & 15);
    const uint32_t selA = ((uint32_t)lane >> 4) << 4;
    const uint32_t aBase = smb + S_A + rowA * 128;
    const uint32_t mA = (rowA & 7) << 4;
    const int rowB = (lane & 7) + ((lane & 16) >> 1);
    const uint32_t selB = ((uint32_t)lane & 8) << 1;
    const uint32_t bBase = smb + wOff + rowB * 128;
    const uint32_t mB = (rowB & 7) << 4;
#pragma unroll
    for (int kt = 0; kt < 4; kt++) {
        uint32_t aAddr = aBase + ((32u * kt + selA) ^ mA);
        uint32_t a0[4], a1[4];
        LDSM4(a0, aAddr);
        LDSM4(a1, aAddr + 2048);
        uint32_t bx = (32u * kt + selB) ^ mB;
#pragma unroll
        for (int np = 0; np < 4; np++) {
            uint32_t bAddr = bBase + np * 2048 + bx;
            uint32_t bh[4], bl[4];
            LDSM4(bh, bAddr);
            LDSM4(bl, bAddr + 8192);
            MMA16(acc[0][2 * np], a0, bh[0], bh[1]);
            MMA16(acc[0][2 * np], a0, bl[0], bl[1]);
            MMA16(acc[0][2 * np + 1], a0, bh[2], bh[3]);
            MMA16(acc[0][2 * np + 1], a0, bl[2], bl[3]);
            MMA16(acc[1][2 * np], a1, bh[0], bh[1]);
            MMA16(acc[1][2 * np], a1, bl[0], bl[1]);
            MMA16(acc[1][2 * np + 1], a1, bh[2], bh[3]);
            MMA16(acc[1][2 * np + 1], a1, bl[2], bl[3]);
        }
    }
}

// GEMM with A fragments in registers (fp16), 2-pass B
__device__ __forceinline__ void gemm_regA(uint32_t smb, uint32_t wOff, int lane,
                                          const uint32_t mf[2][16],
                                          float acc[2][8][4]) {
    const int rowB = (lane & 7) + ((lane & 16) >> 1);
    const uint32_t selB = ((uint32_t)lane & 8) << 1;
    const uint32_t bBase = smb + wOff + rowB * 128;
    const uint32_t mB = (rowB & 7) << 4;
#pragma unroll
    for (int kt = 0; kt < 4; kt++) {
        uint32_t bx = (32u * kt + selB) ^ mB;
        const uint32_t* f0 = &mf[0][4 * kt];
        const uint32_t* f1 = &mf[1][4 * kt];
#pragma unroll
        for (int np = 0; np < 4; np++) {
            uint32_t bAddr = bBase + np * 2048 + bx;
            uint32_t bh[4], bl[4];
            LDSM4(bh, bAddr);
            LDSM4(bl, bAddr + 8192);
            MMA16(acc[0][2 * np], f0, bh[0], bh[1]);
            MMA16(acc[0][2 * np], f0, bl[0], bl[1]);
            MMA16(acc[0][2 * np + 1], f0, bh[2], bh[3]);
            MMA16(acc[0][2 * np + 1], f0, bl[2], bl[3]);
            MMA16(acc[1][2 * np], f1, bh[0], bh[1]);
            MMA16(acc[1][2 * np], f1, bl[0], bl[1]);
            MMA16(acc[1][2 * np + 1], f1, bh[2], bh[3]);
            MMA16(acc[1][2 * np + 1], f1, bl[2], bl[3]);
        }
    }
}

// ---------------- init ----------------
__global__ void k_init(const float* __restrict__ feat,
                       const float* __restrict__ w_emb,
                       const float* __restrict__ b_emb,
                       const float* __restrict__ pos,
                       const float* __restrict__ we1,
                       const float* __restrict__ be1) {
    __shared__ float fs[4][FD], hs[4][HD];
    int g = threadIdx.x >> 6, j = threadIdx.x & 63;
    int t = blockIdx.x * 4 + g;
    if (j < FD) fs[g][j] = feat[t * FD + j];
    __syncthreads();
    float acc = b_emb[j];
#pragma unroll
    for (int i = 0; i < FD; i++) acc += fs[g][i] * w_emb[i * HD + j];
    g_h[t * HD + j] = acc;
    hs[g][j] = acc;
    if (j < 8) g_x8[t * 8 + j] = (j < 6) ? pos[t * 3 + (j % 3)] : 0.0f;
    __syncthreads();
    if (j < 32) {
        const float* w = we1;
        float alo = 0, ahi = 0;
        float blo = be1[j], bhi = be1[j + 32];
#pragma unroll 8
        for (int i = 0; i < HD; i++) {
            float hv = hs[g][i];
            alo += hv * w[i * HD + j];
            ahi += hv * w[i * HD + j + 32];
            blo += hv * w[(64 + i) * HD + j];
            bhi += hv * w[(64 + i) * HD + j + 32];
        }
        g_A2[t * 32 + j] = make_float2(alo, ahi);
        g_B2[t * 32 + j] = make_float2(blo, bhi);
    }
}

// ---------------- mma.sync edge kernel: one block (128 thr) per receiver ---
__global__ void __launch_bounds__(128, 4)
k_edge_mma(const float* __restrict__ we1, const float* __restrict__ we2,
           const float* __restrict__ be2, const float* __restrict__ wx1,
           const float* __restrict__ bx1, const float* __restrict__ wx2,
           int layer) {
    const float* we1l = we1 + layer * 130 * HD;
    const float* we2l = we2 + layer * HD * HD;
    const float* wx1l = wx1 + layer * HD * HD;
    const float* wx2l = wx2 + layer * HD * 2;
    const float* be2l = be2 + layer * HD;
    const float* bx1l = bx1 + layer * HD;

    extern __shared__ char sm[];
    char* aux = sm + S_AUX;
    float4* swq  = (float4*)(aux + AX_WQ);
    float2* sbr  = (float2*)(aux + AX_BR);
    float*  sbe2 = (float*)(aux + AX_BE2);
    float*  sbx1 = (float*)(aux + AX_BX1);
    float2* swx2 = (float2*)(aux + AX_WX2);
    float*  wpart = (float*)(aux + AX_WPART);
    float*  sphi = (float*)(aux + AX_SPHI);
    float*  sxu  = (float*)(aux + AX_SXU);

    const int r = blockIdx.x;
    const int tid = threadIdx.x;
    const int warp = tid >> 5, lane = tid & 31;
    const int tig = lane & 3, gid = lane >> 2;
    const uint32_t smb = smem_u32(sm);

    // ---- preload weights as W^T[n][k] fp16 hi/lo, SW128 rows ----
    {
        int n = tid & 63, kh = tid >> 6;
        float wv[32];
#pragma unroll 8
        for (int kk = 0; kk < 32; kk++) wv[kk] = we2l[(32 * kh + kk) * 64 + n];
#pragma unroll
        for (int jj = 0; jj < 4; jj++) {
            uint32_t hp[4], lp[4];
#pragma unroll
            for (int q = 0; q < 4; q++) {
                float t0 = wv[8 * jj + 2 * q], t1 = wv[8 * jj + 2 * q + 1];
                __half2 H = __floats2half2_rn(t0, t1);
                hp[q] = *reinterpret_cast<uint32_t*>(&H);
                float r0 = t0 - __low2float(H);
                float r1 = t1 - __high2float(H);
                lp[q] = packh2(r0, r1);
            }
            uint32_t sw = sw128((uint32_t)(n * 128 + kh * 64 + jj * 16));
            *(uint4*)(sm + S_W2H + sw) = make_uint4(hp[0], hp[1], hp[2], hp[3]);
            *(uint4*)(sm + S_W2L + sw) = make_uint4(lp[0], lp[1], lp[2], lp[3]);
        }
#pragma unroll 8
        for (int kk = 0; kk < 32; kk++) wv[kk] = wx1l[(32 * kh + kk) * 64 + n];
#pragma unroll
        for (int jj = 0; jj < 4; jj++) {
            uint32_t hp[4], lp[4];
#pragma unroll
            for (int q = 0; q < 4; q++) {
                float t0 = wv[8 * jj + 2 * q], t1 = wv[8 * jj + 2 * q + 1];
                __half2 H = __floats2half2_rn(t0, t1);
                hp[q] = *reinterpret_cast<uint32_t*>(&H);
                float r0 = t0 - __low2float(H);
                float r1 = t1 - __high2float(H);
                lp[q] = packh2(r0, r1);
            }
            uint32_t sw = sw128((uint32_t)(n * 128 + kh * 64 + jj * 16));
            *(uint4*)(sm + S_WXH + sw) = make_uint4(hp[0], hp[1], hp[2], hp[3]);
            *(uint4*)(sm + S_WXL + sw) = make_uint4(lp[0], lp[1], lp[2], lp[3]);
        }
    }
    if (tid < 32) {
        swq[tid] = make_float4(we1l[8192 + tid], we1l[8256 + tid],
                               we1l[8192 + 32 + tid], we1l[8256 + 32 + tid]);
        sbr[tid] = g_B2[r * 32 + tid];
    }
    if (tid < 64) {
        sbe2[tid] = be2l[tid];
        sbx1[tid] = bx1l[tid];
        swx2[tid] = make_float2(wx2l[2 * tid], wx2l[2 * tid + 1]);
    }
    if (tid < 6) sxu[tid] = 0.0f;
    __syncthreads();

    const float4 xra = *(const float4*)&g_x8[r * 8];
    const float4 xrb = *(const float4*)&g_x8[r * 8 + 4];

    float aggv[16];
#pragma unroll
    for (int i = 0; i < 16; i++) aggv[i] = 0.0f;
    float xacc[6] = {0, 0, 0, 0, 0, 0};

    for (int tile = 0; tile < 6; tile++) {
        const int s0 = tile * 128;
        const int s = s0 + tid;

        // ---- edge geometry (thread owns edge row tid) ----
        float4 xa = __ldg((const float4*)&g_x8[s * 8]);
        float4 xb = __ldg((const float4*)&g_x8[s * 8 + 4]);
        float d0 = xa.x - xra.x, d1 = xa.y - xra.y, d2 = xa.z - xra.z;
        float d3 = xa.w - xra.w, d4 = xb.x - xrb.x, d5 = xb.y - xrb.y;
        float sq0 = d0 * d0 + d1 * d1 + d2 * d2;
        float sq1 = d3 * d3 + d4 * d4 + d5 * d5;
        float r0 = __fdividef(1.0f, __fsqrt_rn(sq0 + 1e-8f) + 1.0f);
        float r1 = __fdividef(1.0f, __fsqrt_rn(sq1 + 1e-8f) + 1.0f);
        float sd0 = d0 * r0, sd1 = d1 * r0, sd2 = d2 * r0;
        float sd3 = d3 * r1, sd4 = d4 * r1, sd5 = d5 * r1;

        // ---- t-fill (fp16 A tile for GEMM1) ----
        {
            float tv[64];
            const float4* arow = (const float4*)&g_A2[s * 32];
#pragma unroll
            for (int i2 = 0; i2 < 16; i2++) {
                float4 a4 = __ldg(&arow[i2]);
                int i = 2 * i2;
                {
                    float4 wq = swq[i]; float2 br = sbr[i];
                    tv[i]      = silu(a4.x + br.x + sq0 * wq.x + sq1 * wq.y);
                    tv[i + 32] = silu(a4.y + br.y + sq0 * wq.z + sq1 * wq.w);
                }
                {
                    float4 wq = swq[i + 1]; float2 br = sbr[i + 1];
                    tv[i + 1]  = silu(a4.z + br.x + sq0 * wq.x + sq1 * wq.y);
                    tv[i + 33] = silu(a4.w + br.y + sq0 * wq.z + sq1 * wq.w);
                }
            }
#pragma unroll
            for (int j = 0; j < 8; j++) {
                uint32_t hp[4];
#pragma unroll
                for (int q = 0; q < 4; q++)
                    hp[q] = packh2(tv[8 * j + 2 * q], tv[8 * j + 2 * q + 1]);
                uint32_t sw = sw128((uint32_t)(tid * 128 + j * 16));
                *(uint4*)(sm + S_A + sw) = make_uint4(hp[0], hp[1], hp[2], hp[3]);
            }
        }
        __syncwarp();

        // ---- GEMM 1: m_pre = t @ we2 + be2 ----
        float acc[2][8][4];
        {
            int n0 = 2 * tig;
#pragma unroll
            for (int nt = 0; nt < 8; nt++) {
                float2 b = *(const float2*)&sbe2[8 * nt + n0];
                acc[0][nt][0] = b.x; acc[0][nt][1] = b.y;
                acc[0][nt][2] = b.x; acc[0][nt][3] = b.y;
                acc[1][nt][0] = b.x; acc[1][nt][1] = b.y;
                acc[1][nt][2] = b.x; acc[1][nt][3] = b.y;
            }
        }
        gemm_smemA(smb, S_W2H, warp, lane, acc);

        // ---- epilogue 1: m = silu(.)*mask ; agg ; fp16 fragments in regs --
        uint32_t mf[2][16];
#pragma unroll
        for (int mt = 0; mt < 2; mt++) {
            int rA = 32 * warp + 16 * mt + gid;
            float vA = (s0 + rA != r) ? 1.0f : 0.0f;
            float vB = (s0 + rA + 8 != r) ? 1.0f : 0.0f;
#pragma unroll
            for (int nt = 0; nt < 8; nt++) {
                float m0 = silu(acc[mt][nt][0]) * vA;
                float m1 = silu(acc[mt][nt][1]) * vA;
                float m2 = silu(acc[mt][nt][2]) * vB;
                float m3 = silu(acc[mt][nt][3]) * vB;
                aggv[2 * nt]     += m0 + m2;
                aggv[2 * nt + 1] += m1 + m3;
                mf[mt][2 * nt]     = packh2(m0, m1);
                mf[mt][2 * nt + 1] = packh2(m2, m3);
            }
        }

        // ---- GEMM 2: p_pre = m @ wx1 + bx1 (A from registers) ----
        {
            int n0 = 2 * tig;
#pragma unroll
            for (int nt = 0; nt < 8; nt++) {
                float2 b = *(const float2*)&sbx1[8 * nt + n0];
                acc[0][nt][0] = b.x; acc[0][nt][1] = b.y;
                acc[0][nt][2] = b.x; acc[0][nt][3] = b.y;
                acc[1][nt][0] = b.x; acc[1][nt][1] = b.y;
                acc[1][nt][2] = b.x; acc[1][nt][3] = b.y;
            }
        }
        gemm_regA(smb, S_WXH, lane, mf, acc);

        // ---- epilogue 2: q = silu(p); phi = q @ wx2 (quad-partial) ----
        {
            float ph[4][2] = {{0, 0}, {0, 0}, {0, 0}, {0, 0}};
#pragma unroll
            for (int mt = 0; mt < 2; mt++) {
#pragma unroll
                for (int nt = 0; nt < 8; nt++) {
                    int n0 = 8 * nt + 2 * tig;
                    float4 w = *(const float4*)&swx2[n0];
                    float q0 = silu(acc[mt][nt][0]);
                    float q1 = silu(acc[mt][nt][1]);
                    float q2 = silu(acc[mt][nt][2]);
                    float q3 = silu(acc[mt][nt][3]);
                    ph[2 * mt][0]     += q0 * w.x + q1 * w.z;
                    ph[2 * mt][1]     += q0 * w.y + q1 * w.w;
                    ph[2 * mt + 1][0] += q2 * w.x + q3 * w.z;
                    ph[2 * mt + 1][1] += q2 * w.y + q3 * w.w;
                }
            }
#pragma unroll
            for (int k = 0; k < 4; k++) {
#pragma unroll
                for (int c = 0; c < 2; c++) {
                    ph[k][c] += __shfl_xor_sync(0xffffffffu, ph[k][c], 1);
                    ph[k][c] += __shfl_xor_sync(0xffffffffu, ph[k][c], 2);
                }
            }
            if (tig == 0) {
#pragma unroll
                for (int k = 0; k < 4; k++) {
                    int row = 32 * warp + 16 * (k >> 1) + 8 * (k & 1) + gid;
                    sphi[row * 2] = ph[k][0];
                    sphi[row * 2 + 1] = ph[k][1];
                }
            }
        }
        __syncwarp();
        {
            float2 p = *(const float2*)&sphi[tid * 2];
            xacc[0] += p.x * sd0; xacc[1] += p.x * sd1; xacc[2] += p.x * sd2;
            xacc[3] += p.y * sd3; xacc[4] += p.y * sd4; xacc[5] += p.y * sd5;
        }
        __syncwarp();
    }

    // ---- reductions ----
#pragma unroll
    for (int i = 0; i < 16; i++) {
        aggv[i] += __shfl_xor_sync(0xffffffffu, aggv[i], 4);
        aggv[i] += __shfl_xor_sync(0xffffffffu, aggv[i], 8);
        aggv[i] += __shfl_xor_sync(0xffffffffu, aggv[i], 16);
    }
    if (lane < 4) {
#pragma unroll
        for (int nt = 0; nt < 8; nt++) {
            wpart[warp * 64 + 8 * nt + 2 * lane]     = aggv[2 * nt];
            wpart[warp * 64 + 8 * nt + 2 * lane + 1] = aggv[2 * nt + 1];
        }
    }
#pragma unroll
    for (int c = 0; c < 6; c++) {
        float v = xacc[c];
#pragma unroll
        for (int off = 16; off > 0; off >>= 1)
            v += __shfl_xor_sync(0xffffffffu, v, off);
        if (lane == 0) atomicAdd(&sxu[c], v);
    }
    __syncthreads();
    if (tid < 64)
        g_agg[r * HD + tid] = wpart[tid] + wpart[64 + tid] +
                              wpart[128 + tid] + wpart[192 + tid];
    if (tid < 6) g_xupd[r * 6 + tid] = sxu[tid];
}

// ---------------- node update (+ fused A/B precompute) ----------------
__global__ void k_update(const float* __restrict__ wh1,
                         const float* __restrict__ bh1,
                         const float* __restrict__ wh2,
                         const float* __restrict__ bh2,
                         const float* __restrict__ we1,
                         const float* __restrict__ be1,
                         int layer, int next_layer) {
    __shared__ float hs[4][HD], as[4][HD], us[4][HD];
    int g = threadIdx.x >> 6, j = threadIdx.x & 63;
    int t = blockIdx.x * 4 + g;
    const float* w1 = wh1 + layer * 128 * HD;
    const float* w2 = wh2 + layer * HD * HD;
    hs[g][j] = g_h[t * HD + j];
    as[g][j] = g_agg[t * HD + j];
    __syncthreads();
    float u = bh1[layer * HD + j];
#pragma unroll 8
    for (int i = 0; i < HD; i++) u += hs[g][i] * w1[i * HD + j];
#pragma unroll 8
    for (int i = 0; i < HD; i++) u += as[g][i] * w1[(64 + i) * HD + j];
    us[g][j] = silu(u);
    __syncthreads();
    float o = bh2[layer * HD + j];
#pragma unroll 8
    for (int i = 0; i < HD; i++) o += us[g][i] * w2[i * HD + j];
    float hn = hs[g][j] + o;
    g_h[t * HD + j] = hn;
    if (j < 6) g_x8[t * 8 + j] += g_xupd[t * 6 + j] * INV_T1;
    if (next_layer < LL) {
        hs[g][j] = hn;
        __syncthreads();
        const float* w = we1 + next_layer * 130 * HD;
        if (j < 32) {
            float alo = 0, ahi = 0;
            float blo = be1[next_layer * HD + j], bhi = be1[next_layer * HD + j + 32];
#pragma unroll 8
            for (int i = 0; i < HD; i++) {
                float hv = hs[g][i];
                alo += hv * w[i * HD + j];
                ahi += hv * w[i * HD + j + 32];
                blo += hv * w[(64 + i) * HD + j];
                bhi += hv * w[(64 + i) * HD + j + 32];
            }
            g_A2[t * 32 + j] = make_float2(alo, ahi);
            g_B2[t * 32 + j] = make_float2(blo, bhi);
        }
    }
}

// ---------------- final head ----------------
__global__ void k_final(const float* __restrict__ pos,
                        const float* __restrict__ w_head,
                        const float* __restrict__ b_head,
                        float* __restrict__ out) {
    __shared__ float hs[4][HD];
    int g = threadIdx.x >> 6, j = threadIdx.x & 63;
    int t = blockIdx.x * 4 + g;
    hs[g][j] = g_h[t * HD + j];
    __syncthreads();
    float o = b_head[j];
#pragma unroll 8
    for (int i = 0; i < HD; i++) o += hs[g][i] * w_head[i * OUTD + j];
    out[VEC_OUT + t * OUTD + j] = o;
    if (j < 6) out[t * 6 + j] = g_x8[t * 8 + j] - pos[t * 3 + (j % 3)];
}

// ---------------- launch ----------------
extern "C" void kernel_launch(void* const* d_in, const int* in_sizes, int n_in,
                              void* d_out, int out_size) {
    const float* positions = (const float*)d_in[0];
    const float* features  = (const float*)d_in[1];
    const float* w_emb     = (const float*)d_in[2];
    const float* b_emb     = (const float*)d_in[3];
    const float* we1       = (const float*)d_in[4];
    const float* be1       = (const float*)d_in[5];
    const float* we2       = (const float*)d_in[6];
    const float* be2       = (const float*)d_in[7];
    const float* wx1       = (const float*)d_in[8];
    const float* bx1       = (const float*)d_in[9];
    const float* wx2       = (const float*)d_in[10];
    const float* wh1       = (const float*)d_in[11];
    const float* bh1       = (const float*)d_in[12];
    const float* wh2       = (const float*)d_in[13];
    const float* bh2       = (const float*)d_in[14];
    const float* w_head    = (const float*)d_in[15];
    const float* b_head    = (const float*)d_in[16];
    float* out = (float*)d_out;

    cudaFuncSetAttribute(k_edge_mma, cudaFuncAttributeMaxDynamicSharedMemorySize,
                         EDGE_SMEM);

    k_init<<<NT / 4, 256>>>(features, w_emb, b_emb, positions, we1, be1);
    for (int l = 0; l < LL; l++) {
        k_edge_mma<<<NT, 128, EDGE_SMEM>>>(we1, we2, be2, wx1, bx1, wx2, l);
        k_update<<<NT / 4, 256>>>(wh1, bh1, wh2, bh2, we1, be1, l, l + 1);
    }
    k_final<<<NT / 4, 256>>>(positions, w_head, b_head, out);
}

// round 14
// speedup vs baseline: 1.3104x; 1.0486x over previous
#include <cuda_runtime.h>
#include <cuda_fp16.h>
#include <math.h>
#include <stdint.h>

#define NT   768
#define HD   64
#define FD   32
#define LL   2
#define OUTD 64
#define VEC_OUT (NT * 6)
#define INV_T1 (1.0f / 767.0f)

typedef unsigned long long ull;

// ---------------- device scratch ----------------
__device__ float  g_h[NT * HD];
__device__ float  g_x8[NT * 8];
__device__ float2 g_A2[NT * 32];
__device__ float2 g_B2[NT * 32];
__device__ float  g_aggP[2][NT * HD];
__device__ float  g_xupdP[2][NT * 6];
__device__ uint4  g_wpack[LL][4][512];   // [layer][{W2H,W2L,WXH,WXL}][8KB each]

__device__ __forceinline__ float silu(float x) {
    float t;
    asm("tanh.approx.f32 %0, %1;" : "=f"(t) : "f"(0.5f * x));
    return x * fmaf(0.5f, t, 0.5f);
}
__device__ __forceinline__ uint32_t smem_u32(const void* p) {
    uint32_t a;
    asm("{ .reg .u64 t; cvta.to.shared.u64 t, %1; cvt.u32.u64 %0, t; }"
        : "=r"(a) : "l"(p));
    return a;
}
__device__ __forceinline__ uint32_t sw128(uint32_t off) {
    return off ^ ((off >> 3) & 0x70);
}
__device__ __forceinline__ uint32_t packh2(float lo, float hi) {
    __half2 h = __floats2half2_rn(lo, hi);
    return *reinterpret_cast<uint32_t*>(&h);
}

#define LDSM4(r, a) \
    asm volatile("ldmatrix.sync.aligned.m8n8.x4.shared.b16 {%0,%1,%2,%3}, [%4];" \
        : "=r"((r)[0]), "=r"((r)[1]), "=r"((r)[2]), "=r"((r)[3]) : "r"(a))

#define MMA16(d, a, b0, b1) \
    asm volatile("mma.sync.aligned.m16n8k16.row.col.f32.f16.f16.f32 " \
        "{%0,%1,%2,%3},{%4,%5,%6,%7},{%8,%9},{%0,%1,%2,%3};" \
        : "+f"((d)[0]), "+f"((d)[1]), "+f"((d)[2]), "+f"((d)[3]) \
        : "r"((a)[0]), "r"((a)[1]), "r"((a)[2]), "r"((a)[3]), "r"(b0), "r"(b1))

// ---------------- smem layout ----------------
#define S_A   0           // fp16 activation tile: 128 x 64 x 2B = 16KB
#define S_W2H 16384       // we2^T fp16 hi  8KB   (contiguous 32KB block:
#define S_W2L 24576       //                        W2H,W2L,WXH,WXL)
#define S_WXH 32768
#define S_WXL 40960
#define S_AUX 49152
#define AX_WQ    0        // float4[32]  512
#define AX_BR    512      // float2[32]  256
#define AX_BE2   768      // float[64]   256
#define AX_BX1   1024     // float[64]   256
#define AX_WX2   1280     // float2[64]  512
#define AX_WPART 1792     // float[4*64] 1024
#define AX_SPHI  2816     // float[256]  1024
#define AX_SXU   3840     // float[6]+pad
#define EDGE_SMEM (49152 + 3872)

// GEMM: [128 x 64] fp16 A (smem) @ [64 x 64] (fp16 hi/lo weights), 2-pass
__device__ __forceinline__ void gemm_smemA(uint32_t smb, uint32_t wOff, int warp,
                                           int lane, float acc[2][8][4]) {
    const int rowA = 32 * warp + (lane & 15);
    const uint32_t selA = ((uint32_t)lane >> 4) << 4;
    const uint32_t aBase = smb + S_A + rowA * 128;
    const uint32_t mA = (rowA & 7) << 4;
    const int rowB = (lane & 7) + ((lane & 16) >> 1);
    const uint32_t selB = ((uint32_t)lane & 8) << 1;
    const uint32_t bBase = smb + wOff + rowB * 128;
    const uint32_t mB = (rowB & 7) << 4;
#pragma unroll
    for (int kt = 0; kt < 4; kt++) {
        uint32_t aAddr = aBase + ((32u * kt + selA) ^ mA);
        uint32_t a0[4], a1[4];
        LDSM4(a0, aAddr);
        LDSM4(a1, aAddr + 2048);
        uint32_t bx = (32u * kt + selB) ^ mB;
#pragma unroll
        for (int np = 0; np < 4; np++) {
            uint32_t bAddr = bBase + np * 2048 + bx;
            uint32_t bh[4], bl[4];
            LDSM4(bh, bAddr);
            LDSM4(bl, bAddr + 8192);
            MMA16(acc[0][2 * np], a0, bh[0], bh[1]);
            MMA16(acc[0][2 * np], a0, bl[0], bl[1]);
            MMA16(acc[0][2 * np + 1], a0, bh[2], bh[3]);
            MMA16(acc[0][2 * np + 1], a0, bl[2], bl[3]);
            MMA16(acc[1][2 * np], a1, bh[0], bh[1]);
            MMA16(acc[1][2 * np], a1, bl[0], bl[1]);
            MMA16(acc[1][2 * np + 1], a1, bh[2], bh[3]);
            MMA16(acc[1][2 * np + 1], a1, bl[2], bl[3]);
        }
    }
}

// GEMM with A fragments in registers (fp16), 2-pass B
__device__ __forceinline__ void gemm_regA(uint32_t smb, uint32_t wOff, int lane,
                                          const uint32_t mf[2][16],
                                          float acc[2][8][4]) {
    const int rowB = (lane & 7) + ((lane & 16) >> 1);
    const uint32_t selB = ((uint32_t)lane & 8) << 1;
    const uint32_t bBase = smb + wOff + rowB * 128;
    const uint32_t mB = (rowB & 7) << 4;
#pragma unroll
    for (int kt = 0; kt < 4; kt++) {
        uint32_t bx = (32u * kt + selB) ^ mB;
        const uint32_t* f0 = &mf[0][4 * kt];
        const uint32_t* f1 = &mf[1][4 * kt];
#pragma unroll
        for (int np = 0; np < 4; np++) {
            uint32_t bAddr = bBase + np * 2048 + bx;
            uint32_t bh[4], bl[4];
            LDSM4(bh, bAddr);
            LDSM4(bl, bAddr + 8192);
            MMA16(acc[0][2 * np], f0, bh[0], bh[1]);
            MMA16(acc[0][2 * np], f0, bl[0], bl[1]);
            MMA16(acc[0][2 * np + 1], f0, bh[2], bh[3]);
            MMA16(acc[0][2 * np + 1], f0, bl[2], bl[3]);
            MMA16(acc[1][2 * np], f1, bh[0], bh[1]);
            MMA16(acc[1][2 * np], f1, bl[0], bl[1]);
            MMA16(acc[1][2 * np + 1], f1, bh[2], bh[3]);
            MMA16(acc[1][2 * np + 1], f1, bl[2], bl[3]);
        }
    }
}

// ---------------- one-time weight pre-split (fp16 hi/lo, swizzled) --------
__global__ void k_wprep(const float* __restrict__ we2,
                        const float* __restrict__ wx1) {
    int layer = blockIdx.x;
    int tid = threadIdx.x;
    int n = tid & 63, kh = tid >> 6;
#pragma unroll
    for (int mIdx = 0; mIdx < 2; mIdx++) {
        const float* wsrc = (mIdx == 0 ? we2 : wx1) + layer * HD * HD;
        float wv[32];
#pragma unroll 8
        for (int kk = 0; kk < 32; kk++) wv[kk] = wsrc[(32 * kh + kk) * 64 + n];
#pragma unroll
        for (int jj = 0; jj < 4; jj++) {
            uint32_t hp[4], lp[4];
#pragma unroll
            for (int q = 0; q < 4; q++) {
                float t0 = wv[8 * jj + 2 * q], t1 = wv[8 * jj + 2 * q + 1];
                __half2 H = __floats2half2_rn(t0, t1);
                hp[q] = *reinterpret_cast<uint32_t*>(&H);
                float r0 = t0 - __low2float(H);
                float r1 = t1 - __high2float(H);
                lp[q] = packh2(r0, r1);
            }
            uint32_t sw = sw128((uint32_t)(n * 128 + kh * 64 + jj * 16)) >> 4;
            g_wpack[layer][2 * mIdx][sw]     = make_uint4(hp[0], hp[1], hp[2], hp[3]);
            g_wpack[layer][2 * mIdx + 1][sw] = make_uint4(lp[0], lp[1], lp[2], lp[3]);
        }
    }
}

// ---------------- init ----------------
__global__ void k_init(const float* __restrict__ feat,
                       const float* __restrict__ w_emb,
                       const float* __restrict__ b_emb,
                       const float* __restrict__ pos,
                       const float* __restrict__ we1,
                       const float* __restrict__ be1) {
    __shared__ float fs[4][FD], hs[4][HD];
    int g = threadIdx.x >> 6, j = threadIdx.x & 63;
    int t = blockIdx.x * 4 + g;
    if (j < FD) fs[g][j] = feat[t * FD + j];
    __syncthreads();
    float acc = b_emb[j];
#pragma unroll
    for (int i = 0; i < FD; i++) acc += fs[g][i] * w_emb[i * HD + j];
    g_h[t * HD + j] = acc;
    hs[g][j] = acc;
    if (j < 8) g_x8[t * 8 + j] = (j < 6) ? pos[t * 3 + (j % 3)] : 0.0f;
    __syncthreads();
    if (j < 32) {
        const float* w = we1;
        float alo = 0, ahi = 0;
        float blo = be1[j], bhi = be1[j + 32];
#pragma unroll 8
        for (int i = 0; i < HD; i++) {
            float hv = hs[g][i];
            alo += hv * w[i * HD + j];
            ahi += hv * w[i * HD + j + 32];
            blo += hv * w[(64 + i) * HD + j];
            bhi += hv * w[(64 + i) * HD + j + 32];
        }
        g_A2[t * 32 + j] = make_float2(alo, ahi);
        g_B2[t * 32 + j] = make_float2(blo, bhi);
    }
}

// ---------------- edge kernel: TWO blocks (halves) per receiver -----------
__global__ void __launch_bounds__(128, 4)
k_edge_mma(const float* __restrict__ we1, const float* __restrict__ be2,
           const float* __restrict__ bx1, const float* __restrict__ wx2,
           int layer) {
    const float* we1l = we1 + layer * 130 * HD;
    const float* wx2l = wx2 + layer * HD * 2;
    const float* be2l = be2 + layer * HD;
    const float* bx1l = bx1 + layer * HD;

    extern __shared__ char sm[];
    char* aux = sm + S_AUX;
    float4* swq  = (float4*)(aux + AX_WQ);
    float2* sbr  = (float2*)(aux + AX_BR);
    float*  sbe2 = (float*)(aux + AX_BE2);
    float*  sbx1 = (float*)(aux + AX_BX1);
    float2* swx2 = (float2*)(aux + AX_WX2);
    float*  wpart = (float*)(aux + AX_WPART);
    float*  sphi = (float*)(aux + AX_SPHI);
    float*  sxu  = (float*)(aux + AX_SXU);

    const int r  = blockIdx.x >> 1;
    const int hf = blockIdx.x & 1;
    const int tid = threadIdx.x;
    const int warp = tid >> 5, lane = tid & 31;
    const int tig = lane & 3, gid = lane >> 2;
    const uint32_t smb = smem_u32(sm);

    // ---- weight preload: straight 32KB copy, L2-resident ----
    {
        const uint4* wp = &g_wpack[layer][0][0];
        uint4* dst = (uint4*)(sm + S_W2H);
#pragma unroll
        for (int i = 0; i < 16; i++)
            dst[tid + 128 * i] = __ldg(&wp[tid + 128 * i]);
    }
    if (tid < 32) {
        swq[tid] = make_float4(we1l[8192 + tid], we1l[8256 + tid],
                               we1l[8192 + 32 + tid], we1l[8256 + 32 + tid]);
        sbr[tid] = g_B2[r * 32 + tid];
    }
    if (tid < 64) {
        sbe2[tid] = be2l[tid];
        sbx1[tid] = bx1l[tid];
        swx2[tid] = make_float2(wx2l[2 * tid], wx2l[2 * tid + 1]);
    }
    if (tid < 6) sxu[tid] = 0.0f;
    __syncthreads();

    const float4 xra = *(const float4*)&g_x8[r * 8];
    const float4 xrb = *(const float4*)&g_x8[r * 8 + 4];

    float aggv[16];
#pragma unroll
    for (int i = 0; i < 16; i++) aggv[i] = 0.0f;
    float xacc[6] = {0, 0, 0, 0, 0, 0};

    for (int tile = 3 * hf; tile < 3 * hf + 3; tile++) {
        const int s0 = tile * 128;
        const int s = s0 + tid;

        // ---- edge geometry (thread owns edge row tid) ----
        float4 xa = __ldg((const float4*)&g_x8[s * 8]);
        float4 xb = __ldg((const float4*)&g_x8[s * 8 + 4]);
        float d0 = xa.x - xra.x, d1 = xa.y - xra.y, d2 = xa.z - xra.z;
        float d3 = xa.w - xra.w, d4 = xb.x - xrb.x, d5 = xb.y - xrb.y;
        float sq0 = d0 * d0 + d1 * d1 + d2 * d2;
        float sq1 = d3 * d3 + d4 * d4 + d5 * d5;
        float r0 = __fdividef(1.0f, __fsqrt_rn(sq0 + 1e-8f) + 1.0f);
        float r1 = __fdividef(1.0f, __fsqrt_rn(sq1 + 1e-8f) + 1.0f);
        float sd0 = d0 * r0, sd1 = d1 * r0, sd2 = d2 * r0;
        float sd3 = d3 * r1, sd4 = d4 * r1, sd5 = d5 * r1;

        // ---- t-fill (fp16 A tile for GEMM1) ----
        {
            float tv[64];
            const float4* arow = (const float4*)&g_A2[s * 32];
#pragma unroll
            for (int i2 = 0; i2 < 16; i2++) {
                float4 a4 = __ldg(&arow[i2]);
                int i = 2 * i2;
                {
                    float4 wq = swq[i]; float2 br = sbr[i];
                    tv[i]      = silu(a4.x + br.x + sq0 * wq.x + sq1 * wq.y);
                    tv[i + 32] = silu(a4.y + br.y + sq0 * wq.z + sq1 * wq.w);
                }
                {
                    float4 wq = swq[i + 1]; float2 br = sbr[i + 1];
                    tv[i + 1]  = silu(a4.z + br.x + sq0 * wq.x + sq1 * wq.y);
                    tv[i + 33] = silu(a4.w + br.y + sq0 * wq.z + sq1 * wq.w);
                }
            }
#pragma unroll
            for (int j = 0; j < 8; j++) {
                uint32_t hp[4];
#pragma unroll
                for (int q = 0; q < 4; q++)
                    hp[q] = packh2(tv[8 * j + 2 * q], tv[8 * j + 2 * q + 1]);
                uint32_t sw = sw128((uint32_t)(tid * 128 + j * 16));
                *(uint4*)(sm + S_A + sw) = make_uint4(hp[0], hp[1], hp[2], hp[3]);
            }
        }
        __syncwarp();

        // ---- GEMM 1: m_pre = t @ we2 + be2 ----
        float acc[2][8][4];
        {
            int n0 = 2 * tig;
#pragma unroll
            for (int nt = 0; nt < 8; nt++) {
                float2 b = *(const float2*)&sbe2[8 * nt + n0];
                acc[0][nt][0] = b.x; acc[0][nt][1] = b.y;
                acc[0][nt][2] = b.x; acc[0][nt][3] = b.y;
                acc[1][nt][0] = b.x; acc[1][nt][1] = b.y;
                acc[1][nt][2] = b.x; acc[1][nt][3] = b.y;
            }
        }
        gemm_smemA(smb, S_W2H, warp, lane, acc);

        // ---- epilogue 1: m = silu(.)*mask ; agg ; fp16 fragments in regs --
        uint32_t mf[2][16];
#pragma unroll
        for (int mt = 0; mt < 2; mt++) {
            int rA = 32 * warp + 16 * mt + gid;
            float vA = (s0 + rA != r) ? 1.0f : 0.0f;
            float vB = (s0 + rA + 8 != r) ? 1.0f : 0.0f;
#pragma unroll
            for (int nt = 0; nt < 8; nt++) {
                float m0 = silu(acc[mt][nt][0]) * vA;
                float m1 = silu(acc[mt][nt][1]) * vA;
                float m2 = silu(acc[mt][nt][2]) * vB;
                float m3 = silu(acc[mt][nt][3]) * vB;
                aggv[2 * nt]     += m0 + m2;
                aggv[2 * nt + 1] += m1 + m3;
                mf[mt][2 * nt]     = packh2(m0, m1);
                mf[mt][2 * nt + 1] = packh2(m2, m3);
            }
        }

        // ---- GEMM 2: p_pre = m @ wx1 + bx1 (A from registers) ----
        {
            int n0 = 2 * tig;
#pragma unroll
            for (int nt = 0; nt < 8; nt++) {
                float2 b = *(const float2*)&sbx1[8 * nt + n0];
                acc[0][nt][0] = b.x; acc[0][nt][1] = b.y;
                acc[0][nt][2] = b.x; acc[0][nt][3] = b.y;
                acc[1][nt][0] = b.x; acc[1][nt][1] = b.y;
                acc[1][nt][2] = b.x; acc[1][nt][3] = b.y;
            }
        }
        gemm_regA(smb, S_WXH, lane, mf, acc);

        // ---- epilogue 2: q = silu(p); phi = q @ wx2 (quad-partial) ----
        {
            float ph[4][2] = {{0, 0}, {0, 0}, {0, 0}, {0, 0}};
#pragma unroll
            for (int mt = 0; mt < 2; mt++) {
#pragma unroll
                for (int nt = 0; nt < 8; nt++) {
                    int n0 = 8 * nt + 2 * tig;
                    float4 w = *(const float4*)&swx2[n0];
                    float q0 = silu(acc[mt][nt][0]);
                    float q1 = silu(acc[mt][nt][1]);
                    float q2 = silu(acc[mt][nt][2]);
                    float q3 = silu(acc[mt][nt][3]);
                    ph[2 * mt][0]     += q0 * w.x + q1 * w.z;
                    ph[2 * mt][1]     += q0 * w.y + q1 * w.w;
                    ph[2 * mt + 1][0] += q2 * w.x + q3 * w.z;
                    ph[2 * mt + 1][1] += q2 * w.y + q3 * w.w;
                }
            }
#pragma unroll
            for (int k = 0; k < 4; k++) {
#pragma unroll
                for (int c = 0; c < 2; c++) {
                    ph[k][c] += __shfl_xor_sync(0xffffffffu, ph[k][c], 1);
                    ph[k][c] += __shfl_xor_sync(0xffffffffu, ph[k][c], 2);
                }
            }
            if (tig == 0) {
#pragma unroll
                for (int k = 0; k < 4; k++) {
                    int row = 32 * warp + 16 * (k >> 1) + 8 * (k & 1) + gid;
                    sphi[row * 2] = ph[k][0];
                    sphi[row * 2 + 1] = ph[k][1];
                }
            }
        }
        __syncwarp();
        {
            float2 p = *(const float2*)&sphi[tid * 2];
            xacc[0] += p.x * sd0; xacc[1] += p.x * sd1; xacc[2] += p.x * sd2;
            xacc[3] += p.y * sd3; xacc[4] += p.y * sd4; xacc[5] += p.y * sd5;
        }
        __syncwarp();
    }

    // ---- reductions (partial per half) ----
#pragma unroll
    for (int i = 0; i < 16; i++) {
        aggv[i] += __shfl_xor_sync(0xffffffffu, aggv[i], 4);
        aggv[i] += __shfl_xor_sync(0xffffffffu, aggv[i], 8);
        aggv[i] += __shfl_xor_sync(0xffffffffu, aggv[i], 16);
    }
    if (lane < 4) {
#pragma unroll
        for (int nt = 0; nt < 8; nt++) {
            wpart[warp * 64 + 8 * nt + 2 * lane]     = aggv[2 * nt];
            wpart[warp * 64 + 8 * nt + 2 * lane + 1] = aggv[2 * nt + 1];
        }
    }
#pragma unroll
    for (int c = 0; c < 6; c++) {
        float v = xacc[c];
#pragma unroll
        for (int off = 16; off > 0; off >>= 1)
            v += __shfl_xor_sync(0xffffffffu, v, off);
        if (lane == 0) atomicAdd(&sxu[c], v);
    }
    __syncthreads();
    if (tid < 64)
        g_aggP[hf][r * HD + tid] = wpart[tid] + wpart[64 + tid] +
                                   wpart[128 + tid] + wpart[192 + tid];
    if (tid < 6) g_xupdP[hf][r * 6 + tid] = sxu[tid];
}

// ---------------- node update (+ fused A/B precompute) ----------------
__global__ void k_update(const float* __restrict__ wh1,
                         const float* __restrict__ bh1,
                         const float* __restrict__ wh2,
                         const float* __restrict__ bh2,
                         const float* __restrict__ we1,
                         const float* __restrict__ be1,
                         int layer, int next_layer) {
    __shared__ float hs[4][HD], as[4][HD], us[4][HD];
    int g = threadIdx.x >> 6, j = threadIdx.x & 63;
    int t = blockIdx.x * 4 + g;
    const float* w1 = wh1 + layer * 128 * HD;
    const float* w2 = wh2 + layer * HD * HD;
    hs[g][j] = g_h[t * HD + j];
    as[g][j] = g_aggP[0][t * HD + j] + g_aggP[1][t * HD + j];
    __syncthreads();
    float u = bh1[layer * HD + j];
#pragma unroll 8
    for (int i = 0; i < HD; i++) u += hs[g][i] * w1[i * HD + j];
#pragma unroll 8
    for (int i = 0; i < HD; i++) u += as[g][i] * w1[(64 + i) * HD + j];
    us[g][j] = silu(u);
    __syncthreads();
    float o = bh2[layer * HD + j];
#pragma unroll 8
    for (int i = 0; i < HD; i++) o += us[g][i] * w2[i * HD + j];
    float hn = hs[g][j] + o;
    g_h[t * HD + j] = hn;
    if (j < 6)
        g_x8[t * 8 + j] += (g_xupdP[0][t * 6 + j] + g_xupdP[1][t * 6 + j]) * INV_T1;
    if (next_layer < LL) {
        hs[g][j] = hn;
        __syncthreads();
        const float* w = we1 + next_layer * 130 * HD;
        if (j < 32) {
            float alo = 0, ahi = 0;
            float blo = be1[next_layer * HD + j], bhi = be1[next_layer * HD + j + 32];
#pragma unroll 8
            for (int i = 0; i < HD; i++) {
                float hv = hs[g][i];
                alo += hv * w[i * HD + j];
                ahi += hv * w[i * HD + j + 32];
                blo += hv * w[(64 + i) * HD + j];
                bhi += hv * w[(64 + i) * HD + j + 32];
            }
            g_A2[t * 32 + j] = make_float2(alo, ahi);
            g_B2[t * 32 + j] = make_float2(blo, bhi);
        }
    }
}

// ---------------- final head ----------------
__global__ void k_final(const float* __restrict__ pos,
                        const float* __restrict__ w_head,
                        const float* __restrict__ b_head,
                        float* __restrict__ out) {
    __shared__ float hs[4][HD];
    int g = threadIdx.x >> 6, j = threadIdx.x & 63;
    int t = blockIdx.x * 4 + g;
    hs[g][j] = g_h[t * HD + j];
    __syncthreads();
    float o = b_head[j];
#pragma unroll 8
    for (int i = 0; i < HD; i++) o += hs[g][i] * w_head[i * OUTD + j];
    out[VEC_OUT + t * OUTD + j] = o;
    if (j < 6) out[t * 6 + j] = g_x8[t * 8 + j] - pos[t * 3 + (j % 3)];
}

// ---------------- launch ----------------
extern "C" void kernel_launch(void* const* d_in, const int* in_sizes, int n_in,
                              void* d_out, int out_size) {
    const float* positions = (const float*)d_in[0];
    const float* features  = (const float*)d_in[1];
    const float* w_emb     = (const float*)d_in[2];
    const float* b_emb     = (const float*)d_in[3];
    const float* we1       = (const float*)d_in[4];
    const float* be1       = (const float*)d_in[5];
    const float* we2       = (const float*)d_in[6];
    const float* be2       = (const float*)d_in[7];
    const float* wx1       = (const float*)d_in[8];
    const float* bx1       = (const float*)d_in[9];
    const float* wx2       = (const float*)d_in[10];
    const float* wh1       = (const float*)d_in[11];
    const float* bh1       = (const float*)d_in[12];
    const float* wh2       = (const float*)d_in[13];
    const float* bh2       = (const float*)d_in[14];
    const float* w_head    = (const float*)d_in[15];
    const float* b_head    = (const float*)d_in[16];
    float* out = (float*)d_out;

    cudaFuncSetAttribute(k_edge_mma, cudaFuncAttributeMaxDynamicSharedMemorySize,
                         EDGE_SMEM);

    k_wprep<<<LL, 128>>>(we2, wx1);
    k_init<<<NT / 4, 256>>>(features, w_emb, b_emb, positions, we1, be1);
    for (int l = 0; l < LL; l++) {
        k_edge_mma<<<2 * NT, 128, EDGE_SMEM>>>(we1, be2, bx1, wx2, l);
        k_update<<<NT / 4, 256>>>(wh1, bh1, wh2, bh2, we1, be1, l, l + 1);
    }
    k_final<<<NT / 4, 256>>>(positions, w_head, b_head, out);
}

// round 15
// speedup vs baseline: 1.3975x; 1.0665x over previous
#include <cuda_runtime.h>
#include <cuda_fp16.h>
#include <math.h>
#include <stdint.h>

#define NT   768
#define HD   64
#define FD   32
#define LL   2
#define OUTD 64
#define VEC_OUT (NT * 6)
#define INV_T1 (1.0f / 767.0f)

typedef unsigned long long ull;

// ---------------- device scratch ----------------
__device__ float  g_h[NT * HD];
__device__ float  g_x8[NT * 8];
__device__ float2 g_A2[NT * 32];
__device__ float2 g_B2[NT * 32];
__device__ float  g_aggP[2][NT * HD];
__device__ float  g_xupdP[2][NT * 6];
__device__ uint4  g_wpack[LL][4][512];   // [layer][{W2H,W2L,WXH,WXL}][8KB each]

__device__ __forceinline__ float silu(float x) {
    float t;
    asm("tanh.approx.f32 %0, %1;" : "=f"(t) : "f"(0.5f * x));
    return x * fmaf(0.5f, t, 0.5f);
}
__device__ __forceinline__ uint32_t smem_u32(const void* p) {
    uint32_t a;
    asm("{ .reg .u64 t; cvta.to.shared.u64 t, %1; cvt.u32.u64 %0, t; }"
        : "=r"(a) : "l"(p));
    return a;
}
__device__ __forceinline__ uint32_t sw128(uint32_t off) {
    return off ^ ((off >> 3) & 0x70);
}
__device__ __forceinline__ uint32_t packh2(float lo, float hi) {
    __half2 h = __floats2half2_rn(lo, hi);
    return *reinterpret_cast<uint32_t*>(&h);
}

#define LDSM4(r, a) \
    asm volatile("ldmatrix.sync.aligned.m8n8.x4.shared.b16 {%0,%1,%2,%3}, [%4];" \
        : "=r"((r)[0]), "=r"((r)[1]), "=r"((r)[2]), "=r"((r)[3]) : "r"(a))

#define MMA16(d, a, b0, b1) \
    asm volatile("mma.sync.aligned.m16n8k16.row.col.f32.f16.f16.f32 " \
        "{%0,%1,%2,%3},{%4,%5,%6,%7},{%8,%9},{%0,%1,%2,%3};" \
        : "+f"((d)[0]), "+f"((d)[1]), "+f"((d)[2]), "+f"((d)[3]) \
        : "r"((a)[0]), "r"((a)[1]), "r"((a)[2]), "r"((a)[3]), "r"(b0), "r"(b1))

// ---------------- smem layout (edge kernel) ----------------
#define S_A   0           // fp16 activation tile: 128 x 64 x 2B = 16KB
#define S_W2H 16384
#define S_W2L 24576
#define S_WXH 32768
#define S_WXL 40960
#define S_AUX 49152
#define AX_WQ    0
#define AX_BR    512
#define AX_BE2   768
#define AX_BX1   1024
#define AX_WX2   1280
#define AX_WPART 1792
#define AX_SPHI  2816
#define AX_SXU   3840
#define EDGE_SMEM (49152 + 3872)
#define UPD_SMEM  81920    // w1 32KB + w2 16KB + we1_next 32KB
#define INIT_SMEM 40960    // w_emb 8KB + we1[0] rows0-127 32KB
#define FIN_SMEM  16384    // w_head

// GEMM: [128 x 64] fp16 A (smem) @ [64 x 64] (fp16 hi/lo weights), 2-pass
__device__ __forceinline__ void gemm_smemA(uint32_t smb, uint32_t wOff, int warp,
                                           int lane, float acc[2][8][4]) {
    const int rowA = 32 * warp + (lane & 15);
    const uint32_t selA = ((uint32_t)lane >> 4) << 4;
    const uint32_t aBase = smb + S_A + rowA * 128;
    const uint32_t mA = (rowA & 7) << 4;
    const int rowB = (lane & 7) + ((lane & 16) >> 1);
    const uint32_t selB = ((uint32_t)lane & 8) << 1;
    const uint32_t bBase = smb + wOff + rowB * 128;
    const uint32_t mB = (rowB & 7) << 4;
#pragma unroll
    for (int kt = 0; kt < 4; kt++) {
        uint32_t aAddr = aBase + ((32u * kt + selA) ^ mA);
        uint32_t a0[4], a1[4];
        LDSM4(a0, aAddr);
        LDSM4(a1, aAddr + 2048);
        uint32_t bx = (32u * kt + selB) ^ mB;
#pragma unroll
        for (int np = 0; np < 4; np++) {
            uint32_t bAddr = bBase + np * 2048 + bx;
            uint32_t bh[4], bl[4];
            LDSM4(bh, bAddr);
            LDSM4(bl, bAddr + 8192);
            MMA16(acc[0][2 * np], a0, bh[0], bh[1]);
            MMA16(acc[0][2 * np], a0, bl[0], bl[1]);
            MMA16(acc[0][2 * np + 1], a0, bh[2], bh[3]);
            MMA16(acc[0][2 * np + 1], a0, bl[2], bl[3]);
            MMA16(acc[1][2 * np], a1, bh[0], bh[1]);
            MMA16(acc[1][2 * np], a1, bl[0], bl[1]);
            MMA16(acc[1][2 * np + 1], a1, bh[2], bh[3]);
            MMA16(acc[1][2 * np + 1], a1, bl[2], bl[3]);
        }
    }
}

// GEMM with A fragments in registers (fp16), 2-pass B
__device__ __forceinline__ void gemm_regA(uint32_t smb, uint32_t wOff, int lane,
                                          const uint32_t mf[2][16],
                                          float acc[2][8][4]) {
    const int rowB = (lane & 7) + ((lane & 16) >> 1);
    const uint32_t selB = ((uint32_t)lane & 8) << 1;
    const uint32_t bBase = smb + wOff + rowB * 128;
    const uint32_t mB = (rowB & 7) << 4;
#pragma unroll
    for (int kt = 0; kt < 4; kt++) {
        uint32_t bx = (32u * kt + selB) ^ mB;
        const uint32_t* f0 = &mf[0][4 * kt];
        const uint32_t* f1 = &mf[1][4 * kt];
#pragma unroll
        for (int np = 0; np < 4; np++) {
            uint32_t bAddr = bBase + np * 2048 + bx;
            uint32_t bh[4], bl[4];
            LDSM4(bh, bAddr);
            LDSM4(bl, bAddr + 8192);
            MMA16(acc[0][2 * np], f0, bh[0], bh[1]);
            MMA16(acc[0][2 * np], f0, bl[0], bl[1]);
            MMA16(acc[0][2 * np + 1], f0, bh[2], bh[3]);
            MMA16(acc[0][2 * np + 1], f0, bl[2], bl[3]);
            MMA16(acc[1][2 * np], f1, bh[0], bh[1]);
            MMA16(acc[1][2 * np], f1, bl[0], bl[1]);
            MMA16(acc[1][2 * np + 1], f1, bh[2], bh[3]);
            MMA16(acc[1][2 * np + 1], f1, bl[2], bl[3]);
        }
    }
}

// ---------------- one-time weight pre-split (fp16 hi/lo, swizzled) --------
__global__ void k_wprep(const float* __restrict__ we2,
                        const float* __restrict__ wx1) {
    int layer = blockIdx.x;
    int tid = threadIdx.x;
    int n = tid & 63, kh = tid >> 6;
#pragma unroll
    for (int mIdx = 0; mIdx < 2; mIdx++) {
        const float* wsrc = (mIdx == 0 ? we2 : wx1) + layer * HD * HD;
        float wv[32];
#pragma unroll 8
        for (int kk = 0; kk < 32; kk++) wv[kk] = wsrc[(32 * kh + kk) * 64 + n];
#pragma unroll
        for (int jj = 0; jj < 4; jj++) {
            uint32_t hp[4], lp[4];
#pragma unroll
            for (int q = 0; q < 4; q++) {
                float t0 = wv[8 * jj + 2 * q], t1 = wv[8 * jj + 2 * q + 1];
                __half2 H = __floats2half2_rn(t0, t1);
                hp[q] = *reinterpret_cast<uint32_t*>(&H);
                float r0 = t0 - __low2float(H);
                float r1 = t1 - __high2float(H);
                lp[q] = packh2(r0, r1);
            }
            uint32_t sw = sw128((uint32_t)(n * 128 + kh * 64 + jj * 16)) >> 4;
            g_wpack[layer][2 * mIdx][sw]     = make_uint4(hp[0], hp[1], hp[2], hp[3]);
            g_wpack[layer][2 * mIdx + 1][sw] = make_uint4(lp[0], lp[1], lp[2], lp[3]);
        }
    }
}

// ---------------- init (smem-staged weights) ----------------
__global__ void k_init(const float* __restrict__ feat,
                       const float* __restrict__ w_emb,
                       const float* __restrict__ b_emb,
                       const float* __restrict__ pos,
                       const float* __restrict__ we1,
                       const float* __restrict__ be1) {
    extern __shared__ float smw[];           // [0,2048) w_emb ; [2048,10240) we1
    __shared__ float fs[4][FD], hs[4][HD], Ax[4][HD], Bx[4][HD];
    int tid = threadIdx.x;
    int g = tid >> 6, j = tid & 63;
    int t = blockIdx.x * 4 + g;
    {
        float4* d = (float4*)smw;
        const float4* s1 = (const float4*)w_emb;
#pragma unroll
        for (int i = 0; i < 2; i++) d[tid + 256 * i] = __ldg(&s1[tid + 256 * i]);
        const float4* s2 = (const float4*)we1;   // layer 0, rows 0..127
#pragma unroll
        for (int i = 0; i < 8; i++) d[512 + tid + 256 * i] = __ldg(&s2[tid + 256 * i]);
    }
    if (j < FD) fs[g][j] = feat[t * FD + j];
    __syncthreads();
    float acc = b_emb[j];
#pragma unroll
    for (int i = 0; i < FD; i++) acc += fs[g][i] * smw[i * HD + j];
    g_h[t * HD + j] = acc;
    hs[g][j] = acc;
    if (j < 8) g_x8[t * 8 + j] = (j < 6) ? pos[t * 3 + (j % 3)] : 0.0f;
    __syncthreads();
    {
        const float* w = smw + 2048;
        float a = 0, b = be1[j];
#pragma unroll 8
        for (int i = 0; i < HD; i++) {
            float hv = hs[g][i];
            a += hv * w[i * HD + j];
            b += hv * w[(64 + i) * HD + j];
        }
        Ax[g][j] = a; Bx[g][j] = b;
    }
    __syncthreads();
    if (j < 32) {
        g_A2[t * 32 + j] = make_float2(Ax[g][j], Ax[g][j + 32]);
        g_B2[t * 32 + j] = make_float2(Bx[g][j], Bx[g][j + 32]);
    }
}

// ---------------- edge kernel: TWO blocks (halves) per receiver -----------
__global__ void __launch_bounds__(128, 4)
k_edge_mma(const float* __restrict__ we1, const float* __restrict__ be2,
           const float* __restrict__ bx1, const float* __restrict__ wx2,
           int layer) {
    const float* we1l = we1 + layer * 130 * HD;
    const float* wx2l = wx2 + layer * HD * 2;
    const float* be2l = be2 + layer * HD;
    const float* bx1l = bx1 + layer * HD;

    extern __shared__ char sm[];
    char* aux = sm + S_AUX;
    float4* swq  = (float4*)(aux + AX_WQ);
    float2* sbr  = (float2*)(aux + AX_BR);
    float*  sbe2 = (float*)(aux + AX_BE2);
    float*  sbx1 = (float*)(aux + AX_BX1);
    float2* swx2 = (float2*)(aux + AX_WX2);
    float*  wpart = (float*)(aux + AX_WPART);
    float*  sphi = (float*)(aux + AX_SPHI);
    float*  sxu  = (float*)(aux + AX_SXU);

    const int r  = blockIdx.x >> 1;
    const int hf = blockIdx.x & 1;
    const int tid = threadIdx.x;
    const int warp = tid >> 5, lane = tid & 31;
    const int tig = lane & 3, gid = lane >> 2;
    const uint32_t smb = smem_u32(sm);

    {
        const uint4* wp = &g_wpack[layer][0][0];
        uint4* dst = (uint4*)(sm + S_W2H);
#pragma unroll
        for (int i = 0; i < 16; i++)
            dst[tid + 128 * i] = __ldg(&wp[tid + 128 * i]);
    }
    if (tid < 32) {
        swq[tid] = make_float4(we1l[8192 + tid], we1l[8256 + tid],
                               we1l[8192 + 32 + tid], we1l[8256 + 32 + tid]);
        sbr[tid] = g_B2[r * 32 + tid];
    }
    if (tid < 64) {
        sbe2[tid] = be2l[tid];
        sbx1[tid] = bx1l[tid];
        swx2[tid] = make_float2(wx2l[2 * tid], wx2l[2 * tid + 1]);
    }
    if (tid < 6) sxu[tid] = 0.0f;
    __syncthreads();

    const float4 xra = *(const float4*)&g_x8[r * 8];
    const float4 xrb = *(const float4*)&g_x8[r * 8 + 4];

    float aggv[16];
#pragma unroll
    for (int i = 0; i < 16; i++) aggv[i] = 0.0f;
    float xacc[6] = {0, 0, 0, 0, 0, 0};

    for (int tile = 3 * hf; tile < 3 * hf + 3; tile++) {
        const int s0 = tile * 128;
        const int s = s0 + tid;

        float4 xa = __ldg((const float4*)&g_x8[s * 8]);
        float4 xb = __ldg((const float4*)&g_x8[s * 8 + 4]);
        float d0 = xa.x - xra.x, d1 = xa.y - xra.y, d2 = xa.z - xra.z;
        float d3 = xa.w - xra.w, d4 = xb.x - xrb.x, d5 = xb.y - xrb.y;
        float sq0 = d0 * d0 + d1 * d1 + d2 * d2;
        float sq1 = d3 * d3 + d4 * d4 + d5 * d5;
        float r0 = __fdividef(1.0f, __fsqrt_rn(sq0 + 1e-8f) + 1.0f);
        float r1 = __fdividef(1.0f, __fsqrt_rn(sq1 + 1e-8f) + 1.0f);
        float sd0 = d0 * r0, sd1 = d1 * r0, sd2 = d2 * r0;
        float sd3 = d3 * r1, sd4 = d4 * r1, sd5 = d5 * r1;

        {
            float tv[64];
            const float4* arow = (const float4*)&g_A2[s * 32];
#pragma unroll
            for (int i2 = 0; i2 < 16; i2++) {
                float4 a4 = __ldg(&arow[i2]);
                int i = 2 * i2;
                {
                    float4 wq = swq[i]; float2 br = sbr[i];
                    tv[i]      = silu(a4.x + br.x + sq0 * wq.x + sq1 * wq.y);
                    tv[i + 32] = silu(a4.y + br.y + sq0 * wq.z + sq1 * wq.w);
                }
                {
                    float4 wq = swq[i + 1]; float2 br = sbr[i + 1];
                    tv[i + 1]  = silu(a4.z + br.x + sq0 * wq.x + sq1 * wq.y);
                    tv[i + 33] = silu(a4.w + br.y + sq0 * wq.z + sq1 * wq.w);
                }
            }
#pragma unroll
            for (int j = 0; j < 8; j++) {
                uint32_t hp[4];
#pragma unroll
                for (int q = 0; q < 4; q++)
                    hp[q] = packh2(tv[8 * j + 2 * q], tv[8 * j + 2 * q + 1]);
                uint32_t sw = sw128((uint32_t)(tid * 128 + j * 16));
                *(uint4*)(sm + S_A + sw) = make_uint4(hp[0], hp[1], hp[2], hp[3]);
            }
        }
        __syncwarp();

        float acc[2][8][4];
        {
            int n0 = 2 * tig;
#pragma unroll
            for (int nt = 0; nt < 8; nt++) {
                float2 b = *(const float2*)&sbe2[8 * nt + n0];
                acc[0][nt][0] = b.x; acc[0][nt][1] = b.y;
                acc[0][nt][2] = b.x; acc[0][nt][3] = b.y;
                acc[1][nt][0] = b.x; acc[1][nt][1] = b.y;
                acc[1][nt][2] = b.x; acc[1][nt][3] = b.y;
            }
        }
        gemm_smemA(smb, S_W2H, warp, lane, acc);

        uint32_t mf[2][16];
#pragma unroll
        for (int mt = 0; mt < 2; mt++) {
            int rA = 32 * warp + 16 * mt + gid;
            float vA = (s0 + rA != r) ? 1.0f : 0.0f;
            float vB = (s0 + rA + 8 != r) ? 1.0f : 0.0f;
#pragma unroll
            for (int nt = 0; nt < 8; nt++) {
                float m0 = silu(acc[mt][nt][0]) * vA;
                float m1 = silu(acc[mt][nt][1]) * vA;
                float m2 = silu(acc[mt][nt][2]) * vB;
                float m3 = silu(acc[mt][nt][3]) * vB;
                aggv[2 * nt]     += m0 + m2;
                aggv[2 * nt + 1] += m1 + m3;
                mf[mt][2 * nt]     = packh2(m0, m1);
                mf[mt][2 * nt + 1] = packh2(m2, m3);
            }
        }

        {
            int n0 = 2 * tig;
#pragma unroll
            for (int nt = 0; nt < 8; nt++) {
                float2 b = *(const float2*)&sbx1[8 * nt + n0];
                acc[0][nt][0] = b.x; acc[0][nt][1] = b.y;
                acc[0][nt][2] = b.x; acc[0][nt][3] = b.y;
                acc[1][nt][0] = b.x; acc[1][nt][1] = b.y;
                acc[1][nt][2] = b.x; acc[1][nt][3] = b.y;
            }
        }
        gemm_regA(smb, S_WXH, lane, mf, acc);

        {
            float ph[4][2] = {{0, 0}, {0, 0}, {0, 0}, {0, 0}};
#pragma unroll
            for (int mt = 0; mt < 2; mt++) {
#pragma unroll
                for (int nt = 0; nt < 8; nt++) {
                    int n0 = 8 * nt + 2 * tig;
                    float4 w = *(const float4*)&swx2[n0];
                    float q0 = silu(acc[mt][nt][0]);
                    float q1 = silu(acc[mt][nt][1]);
                    float q2 = silu(acc[mt][nt][2]);
                    float q3 = silu(acc[mt][nt][3]);
                    ph[2 * mt][0]     += q0 * w.x + q1 * w.z;
                    ph[2 * mt][1]     += q0 * w.y + q1 * w.w;
                    ph[2 * mt + 1][0] += q2 * w.x + q3 * w.z;
                    ph[2 * mt + 1][1] += q2 * w.y + q3 * w.w;
                }
            }
#pragma unroll
            for (int k = 0; k < 4; k++) {
#pragma unroll
                for (int c = 0; c < 2; c++) {
                    ph[k][c] += __shfl_xor_sync(0xffffffffu, ph[k][c], 1);
                    ph[k][c] += __shfl_xor_sync(0xffffffffu, ph[k][c], 2);
                }
            }
            if (tig == 0) {
#pragma unroll
                for (int k = 0; k < 4; k++) {
                    int row = 32 * warp + 16 * (k >> 1) + 8 * (k & 1) + gid;
                    sphi[row * 2] = ph[k][0];
                    sphi[row * 2 + 1] = ph[k][1];
                }
            }
        }
        __syncwarp();
        {
            float2 p = *(const float2*)&sphi[tid * 2];
            xacc[0] += p.x * sd0; xacc[1] += p.x * sd1; xacc[2] += p.x * sd2;
            xacc[3] += p.y * sd3; xacc[4] += p.y * sd4; xacc[5] += p.y * sd5;
        }
        __syncwarp();
    }

    // ---- reductions (partial per half) ----
#pragma unroll
    for (int i = 0; i < 16; i++) {
        aggv[i] += __shfl_xor_sync(0xffffffffu, aggv[i], 4);
        aggv[i] += __shfl_xor_sync(0xffffffffu, aggv[i], 8);
        aggv[i] += __shfl_xor_sync(0xffffffffu, aggv[i], 16);
    }
    if (lane < 4) {
#pragma unroll
        for (int nt = 0; nt < 8; nt++) {
            wpart[warp * 64 + 8 * nt + 2 * lane]     = aggv[2 * nt];
            wpart[warp * 64 + 8 * nt + 2 * lane + 1] = aggv[2 * nt + 1];
        }
    }
#pragma unroll
    for (int c = 0; c < 6; c++) {
        float v = xacc[c];
#pragma unroll
        for (int off = 16; off > 0; off >>= 1)
            v += __shfl_xor_sync(0xffffffffu, v, off);
        if (lane == 0) atomicAdd(&sxu[c], v);
    }
    __syncthreads();
    if (tid < 64)
        g_aggP[hf][r * HD + tid] = wpart[tid] + wpart[64 + tid] +
                                   wpart[128 + tid] + wpart[192 + tid];
    if (tid < 6) g_xupdP[hf][r * 6 + tid] = sxu[tid];
}

// ---------------- node update (smem-staged weights) ----------------
__global__ void k_update(const float* __restrict__ wh1,
                         const float* __restrict__ bh1,
                         const float* __restrict__ wh2,
                         const float* __restrict__ bh2,
                         const float* __restrict__ we1,
                         const float* __restrict__ be1,
                         int layer, int next_layer) {
    extern __shared__ float smw[];   // [0,8192) w1 ; [8192,12288) w2 ; [12288,20480) we1n
    __shared__ float hs[4][HD], as[4][HD], us[4][HD], Ax[4][HD], Bx[4][HD];
    int tid = threadIdx.x;
    int g = tid >> 6, j = tid & 63;
    int t = blockIdx.x * 4 + g;
    {
        float4* d = (float4*)smw;
        const float4* s1 = (const float4*)(wh1 + layer * 128 * HD);
#pragma unroll
        for (int i = 0; i < 8; i++) d[tid + 256 * i] = __ldg(&s1[tid + 256 * i]);
        const float4* s2 = (const float4*)(wh2 + layer * HD * HD);
#pragma unroll
        for (int i = 0; i < 4; i++) d[2048 + tid + 256 * i] = __ldg(&s2[tid + 256 * i]);
        if (next_layer < LL) {
            const float4* s3 = (const float4*)(we1 + next_layer * 130 * HD);
#pragma unroll
            for (int i = 0; i < 8; i++) d[3072 + tid + 256 * i] = __ldg(&s3[tid + 256 * i]);
        }
    }
    hs[g][j] = g_h[t * HD + j];
    as[g][j] = g_aggP[0][t * HD + j] + g_aggP[1][t * HD + j];
    __syncthreads();
    float u = bh1[layer * HD + j];
#pragma unroll 8
    for (int i = 0; i < HD; i++) u += hs[g][i] * smw[i * HD + j];
#pragma unroll 8
    for (int i = 0; i < HD; i++) u += as[g][i] * smw[(64 + i) * HD + j];
    us[g][j] = silu(u);
    __syncthreads();
    float o = bh2[layer * HD + j];
#pragma unroll 8
    for (int i = 0; i < HD; i++) o += us[g][i] * smw[8192 + i * HD + j];
    float hn = hs[g][j] + o;
    g_h[t * HD + j] = hn;
    if (j < 6)
        g_x8[t * 8 + j] += (g_xupdP[0][t * 6 + j] + g_xupdP[1][t * 6 + j]) * INV_T1;
    if (next_layer < LL) {
        hs[g][j] = hn;
        __syncthreads();
        const float* w = smw + 12288;
        float a = 0, b = be1[next_layer * HD + j];
#pragma unroll 8
        for (int i = 0; i < HD; i++) {
            float hv = hs[g][i];
            a += hv * w[i * HD + j];
            b += hv * w[(64 + i) * HD + j];
        }
        Ax[g][j] = a; Bx[g][j] = b;
        __syncthreads();
        if (j < 32) {
            g_A2[t * 32 + j] = make_float2(Ax[g][j], Ax[g][j + 32]);
            g_B2[t * 32 + j] = make_float2(Bx[g][j], Bx[g][j + 32]);
        }
    }
}

// ---------------- final head (smem-staged) ----------------
__global__ void k_final(const float* __restrict__ pos,
                        const float* __restrict__ w_head,
                        const float* __restrict__ b_head,
                        float* __restrict__ out) {
    extern __shared__ float smw[];    // w_head 4096 floats
    __shared__ float hs[4][HD];
    int tid = threadIdx.x;
    int g = tid >> 6, j = tid & 63;
    int t = blockIdx.x * 4 + g;
    {
        float4* d = (float4*)smw;
        const float4* s1 = (const float4*)w_head;
#pragma unroll
        for (int i = 0; i < 4; i++) d[tid + 256 * i] = __ldg(&s1[tid + 256 * i]);
    }
    hs[g][j] = g_h[t * HD + j];
    __syncthreads();
    float o = b_head[j];
#pragma unroll 8
    for (int i = 0; i < HD; i++) o += hs[g][i] * smw[i * OUTD + j];
    out[VEC_OUT + t * OUTD + j] = o;
    if (j < 6) out[t * 6 + j] = g_x8[t * 8 + j] - pos[t * 3 + (j % 3)];
}

// ---------------- launch ----------------
extern "C" void kernel_launch(void* const* d_in, const int* in_sizes, int n_in,
                              void* d_out, int out_size) {
    const float* positions = (const float*)d_in[0];
    const float* features  = (const float*)d_in[1];
    const float* w_emb     = (const float*)d_in[2];
    const float* b_emb     = (const float*)d_in[3];
    const float* we1       = (const float*)d_in[4];
    const float* be1       = (const float*)d_in[5];
    const float* we2       = (const float*)d_in[6];
    const float* be2       = (const float*)d_in[7];
    const float* wx1       = (const float*)d_in[8];
    const float* bx1       = (const float*)d_in[9];
    const float* wx2       = (const float*)d_in[10];
    const float* wh1       = (const float*)d_in[11];
    const float* bh1       = (const float*)d_in[12];
    const float* wh2       = (const float*)d_in[13];
    const float* bh2       = (const float*)d_in[14];
    const float* w_head    = (const float*)d_in[15];
    const float* b_head    = (const float*)d_in[16];
    float* out = (float*)d_out;

    cudaFuncSetAttribute(k_edge_mma, cudaFuncAttributeMaxDynamicSharedMemorySize,
                         EDGE_SMEM);
    cudaFuncSetAttribute(k_update, cudaFuncAttributeMaxDynamicSharedMemorySize,
                         UPD_SMEM);
    cudaFuncSetAttribute(k_init, cudaFuncAttributeMaxDynamicSharedMemorySize,
                         INIT_SMEM);
    cudaFuncSetAttribute(k_final, cudaFuncAttributeMaxDynamicSharedMemorySize,
                         FIN_SMEM);

    k_wprep<<<LL, 128>>>(we2, wx1);
    k_init<<<NT / 4, 256, INIT_SMEM>>>(features, w_emb, b_emb, positions, we1, be1);
    for (int l = 0; l < LL; l++) {
        k_edge_mma<<<2 * NT, 128, EDGE_SMEM>>>(we1, be2, bx1, wx2, l);
        k_update<<<NT / 4, 256, UPD_SMEM>>>(wh1, bh1, wh2, bh2, we1, be1, l, l + 1);
    }
    k_final<<<NT / 4, 256, FIN_SMEM>>>(positions, w_head, b_head, out);
}

// round 16
// speedup vs baseline: 1.4345x; 1.0264x over previous
#include <cuda_runtime.h>
#include <cuda_fp16.h>
#include <math.h>
#include <stdint.h>

#define NT   768
#define HD   64
#define FD   32
#define LL   2
#define OUTD 64
#define VEC_OUT (NT * 6)
#define INV_T1 (1.0f / 767.0f)

typedef unsigned long long ull;

// ---------------- device scratch ----------------
__device__ float  g_h[NT * HD];
__device__ float  g_x8[NT * 8];
__device__ float2 g_A2[NT * 32];
__device__ float2 g_B2[NT * 32];
__device__ float  g_aggP[2][NT * HD];
__device__ float  g_xupdP[2][NT * 6];
__device__ uint4  g_wpack[LL][4][512];   // [layer][{W2H,W2L,WXH,WXL}][8KB each]

__device__ __forceinline__ float silu(float x) {
    float t;
    asm("tanh.approx.f32 %0, %1;" : "=f"(t) : "f"(0.5f * x));
    return x * fmaf(0.5f, t, 0.5f);
}
__device__ __forceinline__ uint32_t smem_u32(const void* p) {
    uint32_t a;
    asm("{ .reg .u64 t; cvta.to.shared.u64 t, %1; cvt.u32.u64 %0, t; }"
        : "=r"(a) : "l"(p));
    return a;
}
__device__ __forceinline__ uint32_t sw128(uint32_t off) {
    return off ^ ((off >> 3) & 0x70);
}
__device__ __forceinline__ uint32_t packh2(float lo, float hi) {
    __half2 h = __floats2half2_rn(lo, hi);
    return *reinterpret_cast<uint32_t*>(&h);
}

#define LDSM4(r, a) \
    asm volatile("ldmatrix.sync.aligned.m8n8.x4.shared.b16 {%0,%1,%2,%3}, [%4];" \
        : "=r"((r)[0]), "=r"((r)[1]), "=r"((r)[2]), "=r"((r)[3]) : "r"(a))

#define MMA16(d, a, b0, b1) \
    asm volatile("mma.sync.aligned.m16n8k16.row.col.f32.f16.f16.f32 " \
        "{%0,%1,%2,%3},{%4,%5,%6,%7},{%8,%9},{%0,%1,%2,%3};" \
        : "+f"((d)[0]), "+f"((d)[1]), "+f"((d)[2]), "+f"((d)[3]) \
        : "r"((a)[0]), "r"((a)[1]), "r"((a)[2]), "r"((a)[3]), "r"(b0), "r"(b1))

// ---------------- smem layout (edge kernel) ----------------
#define S_A   0
#define S_W2H 16384
#define S_W2L 24576
#define S_WXH 32768
#define S_WXL 40960
#define S_AUX 49152
#define AX_WQ    0
#define AX_BR    512
#define AX_BE2   768
#define AX_BX1   1024
#define AX_WX2   1280
#define AX_WPART 1792
#define AX_SPHI  2816
#define AX_SXU   3840
#define EDGE_SMEM (49152 + 3872)
#define UPD_SMEM    81920   // w1 32KB + w2 16KB + we1_next 32KB
#define UPDFIN_SMEM 65536   // w1 32KB + w2 16KB + w_head 16KB
#define INIT_SMEM   40960   // w_emb 8KB + we1[0] rows0-127 32KB

// GEMM: [128 x 64] fp16 A (smem) @ [64 x 64] (fp16 hi/lo weights), 2-pass
__device__ __forceinline__ void gemm_smemA(uint32_t smb, uint32_t wOff, int warp,
                                           int lane, float acc[2][8][4]) {
    const int rowA = 32 * warp + (lane & 15);
    const uint32_t selA = ((uint32_t)lane >> 4) << 4;
    const uint32_t aBase = smb + S_A + rowA * 128;
    const uint32_t mA = (rowA & 7) << 4;
    const int rowB = (lane & 7) + ((lane & 16) >> 1);
    const uint32_t selB = ((uint32_t)lane & 8) << 1;
    const uint32_t bBase = smb + wOff + rowB * 128;
    const uint32_t mB = (rowB & 7) << 4;
#pragma unroll
    for (int kt = 0; kt < 4; kt++) {
        uint32_t aAddr = aBase + ((32u * kt + selA) ^ mA);
        uint32_t a0[4], a1[4];
        LDSM4(a0, aAddr);
        LDSM4(a1, aAddr + 2048);
        uint32_t bx = (32u * kt + selB) ^ mB;
#pragma unroll
        for (int np = 0; np < 4; np++) {
            uint32_t bAddr = bBase + np * 2048 + bx;
            uint32_t bh[4], bl[4];
            LDSM4(bh, bAddr);
            LDSM4(bl, bAddr + 8192);
            MMA16(acc[0][2 * np], a0, bh[0], bh[1]);
            MMA16(acc[0][2 * np], a0, bl[0], bl[1]);
            MMA16(acc[0][2 * np + 1], a0, bh[2], bh[3]);
            MMA16(acc[0][2 * np + 1], a0, bl[2], bl[3]);
            MMA16(acc[1][2 * np], a1, bh[0], bh[1]);
            MMA16(acc[1][2 * np], a1, bl[0], bl[1]);
            MMA16(acc[1][2 * np + 1], a1, bh[2], bh[3]);
            MMA16(acc[1][2 * np + 1], a1, bl[2], bl[3]);
        }
    }
}

// GEMM with A fragments in registers (fp16), 2-pass B
__device__ __forceinline__ void gemm_regA(uint32_t smb, uint32_t wOff, int lane,
                                          const uint32_t mf[2][16],
                                          float acc[2][8][4]) {
    const int rowB = (lane & 7) + ((lane & 16) >> 1);
    const uint32_t selB = ((uint32_t)lane & 8) << 1;
    const uint32_t bBase = smb + wOff + rowB * 128;
    const uint32_t mB = (rowB & 7) << 4;
#pragma unroll
    for (int kt = 0; kt < 4; kt++) {
        uint32_t bx = (32u * kt + selB) ^ mB;
        const uint32_t* f0 = &mf[0][4 * kt];
        const uint32_t* f1 = &mf[1][4 * kt];
#pragma unroll
        for (int np = 0; np < 4; np++) {
            uint32_t bAddr = bBase + np * 2048 + bx;
            uint32_t bh[4], bl[4];
            LDSM4(bh, bAddr);
            LDSM4(bl, bAddr + 8192);
            MMA16(acc[0][2 * np], f0, bh[0], bh[1]);
            MMA16(acc[0][2 * np], f0, bl[0], bl[1]);
            MMA16(acc[0][2 * np + 1], f0, bh[2], bh[3]);
            MMA16(acc[0][2 * np + 1], f0, bl[2], bl[3]);
            MMA16(acc[1][2 * np], f1, bh[0], bh[1]);
            MMA16(acc[1][2 * np], f1, bl[0], bl[1]);
            MMA16(acc[1][2 * np + 1], f1, bh[2], bh[3]);
            MMA16(acc[1][2 * np + 1], f1, bl[2], bl[3]);
        }
    }
}

// ---------------- init (+ fused weight pre-split blocks) ----------------
__global__ void k_init(const float* __restrict__ feat,
                       const float* __restrict__ w_emb,
                       const float* __restrict__ b_emb,
                       const float* __restrict__ pos,
                       const float* __restrict__ we1,
                       const float* __restrict__ be1,
                       const float* __restrict__ we2,
                       const float* __restrict__ wx1) {
    int tid = threadIdx.x;
    if (blockIdx.x >= NT / 4) {
        // ---- weight pre-split for layer (blockIdx.x - NT/4) ----
        if (tid >= 128) return;
        int layer = blockIdx.x - NT / 4;
        int n = tid & 63, kh = tid >> 6;
#pragma unroll
        for (int mIdx = 0; mIdx < 2; mIdx++) {
            const float* wsrc = (mIdx == 0 ? we2 : wx1) + layer * HD * HD;
            float wv[32];
#pragma unroll 8
            for (int kk = 0; kk < 32; kk++) wv[kk] = wsrc[(32 * kh + kk) * 64 + n];
#pragma unroll
            for (int jj = 0; jj < 4; jj++) {
                uint32_t hp[4], lp[4];
#pragma unroll
                for (int q = 0; q < 4; q++) {
                    float t0 = wv[8 * jj + 2 * q], t1 = wv[8 * jj + 2 * q + 1];
                    __half2 H = __floats2half2_rn(t0, t1);
                    hp[q] = *reinterpret_cast<uint32_t*>(&H);
                    float r0 = t0 - __low2float(H);
                    float r1 = t1 - __high2float(H);
                    lp[q] = packh2(r0, r1);
                }
                uint32_t sw = sw128((uint32_t)(n * 128 + kh * 64 + jj * 16)) >> 4;
                g_wpack[layer][2 * mIdx][sw]     = make_uint4(hp[0], hp[1], hp[2], hp[3]);
                g_wpack[layer][2 * mIdx + 1][sw] = make_uint4(lp[0], lp[1], lp[2], lp[3]);
            }
        }
        return;
    }
    extern __shared__ float smw[];           // [0,2048) w_emb ; [2048,10240) we1
    __shared__ float fs[4][FD], hs[4][HD], Ax[4][HD], Bx[4][HD];
    int g = tid >> 6, j = tid & 63;
    int t = blockIdx.x * 4 + g;
    {
        float4* d = (float4*)smw;
        const float4* s1 = (const float4*)w_emb;
#pragma unroll
        for (int i = 0; i < 2; i++) d[tid + 256 * i] = __ldg(&s1[tid + 256 * i]);
        const float4* s2 = (const float4*)we1;
#pragma unroll
        for (int i = 0; i < 8; i++) d[512 + tid + 256 * i] = __ldg(&s2[tid + 256 * i]);
    }
    if (j < FD) fs[g][j] = feat[t * FD + j];
    __syncthreads();
    float acc = b_emb[j];
#pragma unroll
    for (int i = 0; i < FD; i++) acc += fs[g][i] * smw[i * HD + j];
    g_h[t * HD + j] = acc;
    hs[g][j] = acc;
    if (j < 8) g_x8[t * 8 + j] = (j < 6) ? pos[t * 3 + (j % 3)] : 0.0f;
    __syncthreads();
    {
        const float* w = smw + 2048;
        float a = 0, b = be1[j];
#pragma unroll 8
        for (int i = 0; i < HD; i++) {
            float hv = hs[g][i];
            a += hv * w[i * HD + j];
            b += hv * w[(64 + i) * HD + j];
        }
        Ax[g][j] = a; Bx[g][j] = b;
    }
    __syncthreads();
    if (j < 32) {
        g_A2[t * 32 + j] = make_float2(Ax[g][j], Ax[g][j + 32]);
        g_B2[t * 32 + j] = make_float2(Bx[g][j], Bx[g][j + 32]);
    }
}

// ---------------- edge kernel: TWO blocks (halves) per receiver -----------
__global__ void __launch_bounds__(128, 4)
k_edge_mma(const float* __restrict__ we1, const float* __restrict__ be2,
           const float* __restrict__ bx1, const float* __restrict__ wx2,
           int layer) {
    const float* we1l = we1 + layer * 130 * HD;
    const float* wx2l = wx2 + layer * HD * 2;
    const float* be2l = be2 + layer * HD;
    const float* bx1l = bx1 + layer * HD;

    extern __shared__ char sm[];
    char* aux = sm + S_AUX;
    float4* swq  = (float4*)(aux + AX_WQ);
    float2* sbr  = (float2*)(aux + AX_BR);
    float*  sbe2 = (float*)(aux + AX_BE2);
    float*  sbx1 = (float*)(aux + AX_BX1);
    float2* swx2 = (float2*)(aux + AX_WX2);
    float*  wpart = (float*)(aux + AX_WPART);
    float*  sphi = (float*)(aux + AX_SPHI);
    float*  sxu  = (float*)(aux + AX_SXU);

    const int r  = blockIdx.x >> 1;
    const int hf = blockIdx.x & 1;
    const int tid = threadIdx.x;
    const int warp = tid >> 5, lane = tid & 31;
    const int tig = lane & 3, gid = lane >> 2;
    const uint32_t smb = smem_u32(sm);

    {
        const uint4* wp = &g_wpack[layer][0][0];
        uint4* dst = (uint4*)(sm + S_W2H);
#pragma unroll
        for (int i = 0; i < 16; i++)
            dst[tid + 128 * i] = __ldg(&wp[tid + 128 * i]);
    }
    if (tid < 32) {
        swq[tid] = make_float4(we1l[8192 + tid], we1l[8256 + tid],
                               we1l[8192 + 32 + tid], we1l[8256 + 32 + tid]);
        sbr[tid] = g_B2[r * 32 + tid];
    }
    if (tid < 64) {
        sbe2[tid] = be2l[tid];
        sbx1[tid] = bx1l[tid];
        swx2[tid] = make_float2(wx2l[2 * tid], wx2l[2 * tid + 1]);
    }
    if (tid < 6) sxu[tid] = 0.0f;
    __syncthreads();

    const float4 xra = *(const float4*)&g_x8[r * 8];
    const float4 xrb = *(const float4*)&g_x8[r * 8 + 4];

    float aggv[16];
#pragma unroll
    for (int i = 0; i < 16; i++) aggv[i] = 0.0f;
    float xacc[6] = {0, 0, 0, 0, 0, 0};

    for (int tile = 3 * hf; tile < 3 * hf + 3; tile++) {
        const int s0 = tile * 128;
        const int s = s0 + tid;

        float4 xa = __ldg((const float4*)&g_x8[s * 8]);
        float4 xb = __ldg((const float4*)&g_x8[s * 8 + 4]);
        float d0 = xa.x - xra.x, d1 = xa.y - xra.y, d2 = xa.z - xra.z;
        float d3 = xa.w - xra.w, d4 = xb.x - xrb.x, d5 = xb.y - xrb.y;
        float sq0 = d0 * d0 + d1 * d1 + d2 * d2;
        float sq1 = d3 * d3 + d4 * d4 + d5 * d5;
        float r0 = __fdividef(1.0f, __fsqrt_rn(sq0 + 1e-8f) + 1.0f);
        float r1 = __fdividef(1.0f, __fsqrt_rn(sq1 + 1e-8f) + 1.0f);
        float sd0 = d0 * r0, sd1 = d1 * r0, sd2 = d2 * r0;
        float sd3 = d3 * r1, sd4 = d4 * r1, sd5 = d5 * r1;

        {
            float tv[64];
            const float4* arow = (const float4*)&g_A2[s * 32];
#pragma unroll
            for (int i2 = 0; i2 < 16; i2++) {
                float4 a4 = __ldg(&arow[i2]);
                int i = 2 * i2;
                {
                    float4 wq = swq[i]; float2 br = sbr[i];
                    tv[i]      = silu(a4.x + br.x + sq0 * wq.x + sq1 * wq.y);
                    tv[i + 32] = silu(a4.y + br.y + sq0 * wq.z + sq1 * wq.w);
                }
                {
                    float4 wq = swq[i + 1]; float2 br = sbr[i + 1];
                    tv[i + 1]  = silu(a4.z + br.x + sq0 * wq.x + sq1 * wq.y);
                    tv[i + 33] = silu(a4.w + br.y + sq0 * wq.z + sq1 * wq.w);
                }
            }
#pragma unroll
            for (int j = 0; j < 8; j++) {
                uint32_t hp[4];
#pragma unroll
                for (int q = 0; q < 4; q++)
                    hp[q] = packh2(tv[8 * j + 2 * q], tv[8 * j + 2 * q + 1]);
                uint32_t sw = sw128((uint32_t)(tid * 128 + j * 16));
                *(uint4*)(sm + S_A + sw) = make_uint4(hp[0], hp[1], hp[2], hp[3]);
            }
        }
        __syncwarp();

        float acc[2][8][4];
        {
            int n0 = 2 * tig;
#pragma unroll
            for (int nt = 0; nt < 8; nt++) {
                float2 b = *(const float2*)&sbe2[8 * nt + n0];
                acc[0][nt][0] = b.x; acc[0][nt][1] = b.y;
                acc[0][nt][2] = b.x; acc[0][nt][3] = b.y;
                acc[1][nt][0] = b.x; acc[1][nt][1] = b.y;
                acc[1][nt][2] = b.x; acc[1][nt][3] = b.y;
            }
        }
        gemm_smemA(smb, S_W2H, warp, lane, acc);

        uint32_t mf[2][16];
#pragma unroll
        for (int mt = 0; mt < 2; mt++) {
            int rA = 32 * warp + 16 * mt + gid;
            float vA = (s0 + rA != r) ? 1.0f : 0.0f;
            float vB = (s0 + rA + 8 != r) ? 1.0f : 0.0f;
#pragma unroll
            for (int nt = 0; nt < 8; nt++) {
                float m0 = silu(acc[mt][nt][0]) * vA;
                float m1 = silu(acc[mt][nt][1]) * vA;
                float m2 = silu(acc[mt][nt][2]) * vB;
                float m3 = silu(acc[mt][nt][3]) * vB;
                aggv[2 * nt]     += m0 + m2;
                aggv[2 * nt + 1] += m1 + m3;
                mf[mt][2 * nt]     = packh2(m0, m1);
                mf[mt][2 * nt + 1] = packh2(m2, m3);
            }
        }

        {
            int n0 = 2 * tig;
#pragma unroll
            for (int nt = 0; nt < 8; nt++) {
                float2 b = *(const float2*)&sbx1[8 * nt + n0];
                acc[0][nt][0] = b.x; acc[0][nt][1] = b.y;
                acc[0][nt][2] = b.x; acc[0][nt][3] = b.y;
                acc[1][nt][0] = b.x; acc[1][nt][1] = b.y;
                acc[1][nt][2] = b.x; acc[1][nt][3] = b.y;
            }
        }
        gemm_regA(smb, S_WXH, lane, mf, acc);

        {
            float ph[4][2] = {{0, 0}, {0, 0}, {0, 0}, {0, 0}};
#pragma unroll
            for (int mt = 0; mt < 2; mt++) {
#pragma unroll
                for (int nt = 0; nt < 8; nt++) {
                    int n0 = 8 * nt + 2 * tig;
                    float4 w = *(const float4*)&swx2[n0];
                    float q0 = silu(acc[mt][nt][0]);
                    float q1 = silu(acc[mt][nt][1]);
                    float q2 = silu(acc[mt][nt][2]);
                    float q3 = silu(acc[mt][nt][3]);
                    ph[2 * mt][0]     += q0 * w.x + q1 * w.z;
                    ph[2 * mt][1]     += q0 * w.y + q1 * w.w;
                    ph[2 * mt + 1][0] += q2 * w.x + q3 * w.z;
                    ph[2 * mt + 1][1] += q2 * w.y + q3 * w.w;
                }
            }
#pragma unroll
            for (int k = 0; k < 4; k++) {
#pragma unroll
                for (int c = 0; c < 2; c++) {
                    ph[k][c] += __shfl_xor_sync(0xffffffffu, ph[k][c], 1);
                    ph[k][c] += __shfl_xor_sync(0xffffffffu, ph[k][c], 2);
                }
            }
            if (tig == 0) {
#pragma unroll
                for (int k = 0; k < 4; k++) {
                    int row = 32 * warp + 16 * (k >> 1) + 8 * (k & 1) + gid;
                    sphi[row * 2] = ph[k][0];
                    sphi[row * 2 + 1] = ph[k][1];
                }
            }
        }
        __syncwarp();
        {
            float2 p = *(const float2*)&sphi[tid * 2];
            xacc[0] += p.x * sd0; xacc[1] += p.x * sd1; xacc[2] += p.x * sd2;
            xacc[3] += p.y * sd3; xacc[4] += p.y * sd4; xacc[5] += p.y * sd5;
        }
        __syncwarp();
    }

    // ---- reductions (partial per half) ----
#pragma unroll
    for (int i = 0; i < 16; i++) {
        aggv[i] += __shfl_xor_sync(0xffffffffu, aggv[i], 4);
        aggv[i] += __shfl_xor_sync(0xffffffffu, aggv[i], 8);
        aggv[i] += __shfl_xor_sync(0xffffffffu, aggv[i], 16);
    }
    if (lane < 4) {
#pragma unroll
        for (int nt = 0; nt < 8; nt++) {
            wpart[warp * 64 + 8 * nt + 2 * lane]     = aggv[2 * nt];
            wpart[warp * 64 + 8 * nt + 2 * lane + 1] = aggv[2 * nt + 1];
        }
    }
#pragma unroll
    for (int c = 0; c < 6; c++) {
        float v = xacc[c];
#pragma unroll
        for (int off = 16; off > 0; off >>= 1)
            v += __shfl_xor_sync(0xffffffffu, v, off);
        if (lane == 0) atomicAdd(&sxu[c], v);
    }
    __syncthreads();
    if (tid < 64)
        g_aggP[hf][r * HD + tid] = wpart[tid] + wpart[64 + tid] +
                                   wpart[128 + tid] + wpart[192 + tid];
    if (tid < 6) g_xupdP[hf][r * 6 + tid] = sxu[tid];
}

// ---------------- node update layer 0 (8 nodes/block, 512 thr) ------------
__global__ void k_update(const float* __restrict__ wh1,
                         const float* __restrict__ bh1,
                         const float* __restrict__ wh2,
                         const float* __restrict__ bh2,
                         const float* __restrict__ we1,
                         const float* __restrict__ be1) {
    extern __shared__ float smw[];   // [0,8192) w1 ; [8192,12288) w2 ; [12288,20480) we1n
    __shared__ float hs[8][HD], as[8][HD], us[8][HD], Ax[8][HD], Bx[8][HD];
    int tid = threadIdx.x;
    int g = tid >> 6, j = tid & 63;
    int t = blockIdx.x * 8 + g;
    {
        float4* d = (float4*)smw;
        const float4* s1 = (const float4*)wh1;              // layer 0
#pragma unroll
        for (int i = 0; i < 4; i++) d[tid + 512 * i] = __ldg(&s1[tid + 512 * i]);
        const float4* s2 = (const float4*)wh2;
#pragma unroll
        for (int i = 0; i < 2; i++) d[2048 + tid + 512 * i] = __ldg(&s2[tid + 512 * i]);
        const float4* s3 = (const float4*)(we1 + 130 * HD); // layer 1
#pragma unroll
        for (int i = 0; i < 4; i++) d[3072 + tid + 512 * i] = __ldg(&s3[tid + 512 * i]);
    }
    hs[g][j] = g_h[t * HD + j];
    as[g][j] = g_aggP[0][t * HD + j] + g_aggP[1][t * HD + j];
    __syncthreads();
    float u = bh1[j];
#pragma unroll 8
    for (int i = 0; i < HD; i++) u += hs[g][i] * smw[i * HD + j];
#pragma unroll 8
    for (int i = 0; i < HD; i++) u += as[g][i] * smw[(64 + i) * HD + j];
    us[g][j] = silu(u);
    __syncthreads();
    float o = bh2[j];
#pragma unroll 8
    for (int i = 0; i < HD; i++) o += us[g][i] * smw[8192 + i * HD + j];
    float hn = hs[g][j] + o;
    g_h[t * HD + j] = hn;
    if (j < 6)
        g_x8[t * 8 + j] += (g_xupdP[0][t * 6 + j] + g_xupdP[1][t * 6 + j]) * INV_T1;
    hs[g][j] = hn;
    __syncthreads();
    {
        const float* w = smw + 12288;
        float a = 0, b = be1[HD + j];
#pragma unroll 8
        for (int i = 0; i < HD; i++) {
            float hv = hs[g][i];
            a += hv * w[i * HD + j];
            b += hv * w[(64 + i) * HD + j];
        }
        Ax[g][j] = a; Bx[g][j] = b;
    }
    __syncthreads();
    if (j < 32) {
        g_A2[t * 32 + j] = make_float2(Ax[g][j], Ax[g][j + 32]);
        g_B2[t * 32 + j] = make_float2(Bx[g][j], Bx[g][j + 32]);
    }
}

// ---------------- node update layer 1 + final head (merged) ---------------
__global__ void k_updfin(const float* __restrict__ wh1,
                         const float* __restrict__ bh1,
                         const float* __restrict__ wh2,
                         const float* __restrict__ bh2,
                         const float* __restrict__ pos,
                         const float* __restrict__ w_head,
                         const float* __restrict__ b_head,
                         float* __restrict__ out) {
    extern __shared__ float smw[];   // [0,8192) w1 ; [8192,12288) w2 ; [12288,16384) w_head
    __shared__ float hs[8][HD], as[8][HD], us[8][HD];
    int tid = threadIdx.x;
    int g = tid >> 6, j = tid & 63;
    int t = blockIdx.x * 8 + g;
    {
        float4* d = (float4*)smw;
        const float4* s1 = (const float4*)(wh1 + 128 * HD);   // layer 1
#pragma unroll
        for (int i = 0; i < 4; i++) d[tid + 512 * i] = __ldg(&s1[tid + 512 * i]);
        const float4* s2 = (const float4*)(wh2 + HD * HD);
#pragma unroll
        for (int i = 0; i < 2; i++) d[2048 + tid + 512 * i] = __ldg(&s2[tid + 512 * i]);
        const float4* s3 = (const float4*)w_head;
#pragma unroll
        for (int i = 0; i < 2; i++) d[3072 + tid + 512 * i] = __ldg(&s3[tid + 512 * i]);
    }
    hs[g][j] = g_h[t * HD + j];
    as[g][j] = g_aggP[0][t * HD + j] + g_aggP[1][t * HD + j];
    __syncthreads();
    float u = bh1[HD + j];
#pragma unroll 8
    for (int i = 0; i < HD; i++) u += hs[g][i] * smw[i * HD + j];
#pragma unroll 8
    for (int i = 0; i < HD; i++) u += as[g][i] * smw[(64 + i) * HD + j];
    us[g][j] = silu(u);
    __syncthreads();
    float o = bh2[HD + j];
#pragma unroll 8
    for (int i = 0; i < HD; i++) o += us[g][i] * smw[8192 + i * HD + j];
    float hn = hs[g][j] + o;
    // vectors output
    if (j < 6) {
        float xv = g_x8[t * 8 + j] +
                   (g_xupdP[0][t * 6 + j] + g_xupdP[1][t * 6 + j]) * INV_T1;
        out[t * 6 + j] = xv - pos[t * 3 + (j % 3)];
    }
    hs[g][j] = hn;
    __syncthreads();
    // invariant head
    float oh = b_head[j];
#pragma unroll 8
    for (int i = 0; i < HD; i++) oh += hs[g][i] * smw[12288 + i * OUTD + j];
    out[VEC_OUT + t * OUTD + j] = oh;
}

// ---------------- launch ----------------
extern "C" void kernel_launch(void* const* d_in, const int* in_sizes, int n_in,
                              void* d_out, int out_size) {
    const float* positions = (const float*)d_in[0];
    const float* features  = (const float*)d_in[1];
    const float* w_emb     = (const float*)d_in[2];
    const float* b_emb     = (const float*)d_in[3];
    const float* we1       = (const float*)d_in[4];
    const float* be1       = (const float*)d_in[5];
    const float* we2       = (const float*)d_in[6];
    const float* be2       = (const float*)d_in[7];
    const float* wx1       = (const float*)d_in[8];
    const float* bx1       = (const float*)d_in[9];
    const float* wx2       = (const float*)d_in[10];
    const float* wh1       = (const float*)d_in[11];
    const float* bh1       = (const float*)d_in[12];
    const float* wh2       = (const float*)d_in[13];
    const float* bh2       = (const float*)d_in[14];
    const float* w_head    = (const float*)d_in[15];
    const float* b_head    = (const float*)d_in[16];
    float* out = (float*)d_out;

    cudaFuncSetAttribute(k_edge_mma, cudaFuncAttributeMaxDynamicSharedMemorySize,
                         EDGE_SMEM);
    cudaFuncSetAttribute(k_update, cudaFuncAttributeMaxDynamicSharedMemorySize,
                         UPD_SMEM);
    cudaFuncSetAttribute(k_updfin, cudaFuncAttributeMaxDynamicSharedMemorySize,
                         UPDFIN_SMEM);
    cudaFuncSetAttribute(k_init, cudaFuncAttributeMaxDynamicSharedMemorySize,
                         INIT_SMEM);

    k_init<<<NT / 4 + LL, 256, INIT_SMEM>>>(features, w_emb, b_emb, positions,
                                            we1, be1, we2, wx1);
    k_edge_mma<<<2 * NT, 128, EDGE_SMEM>>>(we1, be2, bx1, wx2, 0);
    k_update<<<NT / 8, 512, UPD_SMEM>>>(wh1, bh1, wh2, bh2, we1, be1);
    k_edge_mma<<<2 * NT, 128, EDGE_SMEM>>>(we1, be2, bx1, wx2, 1);
    k_updfin<<<NT / 8, 512, UPDFIN_SMEM>>>(wh1, bh1, wh2, bh2, positions,
                                           w_head, b_head, out);
}

// round 17
// speedup vs baseline: 1.6417x; 1.1445x over previous
#include <cuda_runtime.h>
#include <cuda_fp16.h>
#include <math.h>
#include <stdint.h>

#define NT   768
#define HD   64
#define FD   32
#define LL   2
#define OUTD 64
#define VEC_OUT (NT * 6)
#define INV_T1 (1.0f / 767.0f)

typedef unsigned long long ull;

// ---------------- device scratch ----------------
__device__ float  g_h[NT * HD];
__device__ float  g_x8[NT * 8];
__device__ __align__(16) uint32_t g_Ah[NT * 32];   // half2 pairs (A[c], A[c+32])
__device__ float2 g_B2[NT * 32];
__device__ float  g_aggP[2][NT * HD];
__device__ float  g_xupdP[2][NT * 6];
__device__ uint4  g_wpack[LL][4][512];   // [layer][{W2H,W2L,WXH,WXL}][8KB each]

__device__ __forceinline__ float silu(float x) {
    float t;
    asm("tanh.approx.f32 %0, %1;" : "=f"(t) : "f"(0.5f * x));
    return x * fmaf(0.5f, t, 0.5f);
}
__device__ __forceinline__ uint32_t smem_u32(const void* p) {
    uint32_t a;
    asm("{ .reg .u64 t; cvta.to.shared.u64 t, %1; cvt.u32.u64 %0, t; }"
        : "=r"(a) : "l"(p));
    return a;
}
__device__ __forceinline__ uint32_t sw128(uint32_t off) {
    return off ^ ((off >> 3) & 0x70);
}
__device__ __forceinline__ uint32_t packh2(float lo, float hi) {
    __half2 h = __floats2half2_rn(lo, hi);
    return *reinterpret_cast<uint32_t*>(&h);
}

#define LDSM4(r, a) \
    asm volatile("ldmatrix.sync.aligned.m8n8.x4.shared.b16 {%0,%1,%2,%3}, [%4];" \
        : "=r"((r)[0]), "=r"((r)[1]), "=r"((r)[2]), "=r"((r)[3]) : "r"(a))

#define MMA16(d, a, b0, b1) \
    asm volatile("mma.sync.aligned.m16n8k16.row.col.f32.f16.f16.f32 " \
        "{%0,%1,%2,%3},{%4,%5,%6,%7},{%8,%9},{%0,%1,%2,%3};" \
        : "+f"((d)[0]), "+f"((d)[1]), "+f"((d)[2]), "+f"((d)[3]) \
        : "r"((a)[0]), "r"((a)[1]), "r"((a)[2]), "r"((a)[3]), "r"(b0), "r"(b1))

// ---------------- smem layout (edge kernel) ----------------
#define S_A   0
#define S_W2H 16384
#define S_W2L 24576
#define S_WXH 32768
#define S_WXL 40960
#define S_AUX 49152
#define AX_WQ    0
#define AX_BR    512
#define AX_BE2   768
#define AX_BX1   1024
#define AX_WX2   1280
#define AX_WPART 1792
#define AX_SPHI  2816
#define AX_SXU   3840
#define EDGE_SMEM (49152 + 3872)
#define UPD_SMEM    81920
#define UPDFIN_SMEM 65536
#define INIT_SMEM   40960

// GEMM: [128 x 64] fp16 A (smem) @ [64 x 64] (fp16 hi/lo weights), 2-pass
__device__ __forceinline__ void gemm_smemA(uint32_t smb, uint32_t wOff, int warp,
                                           int lane, float acc[2][8][4]) {
    const int rowA = 32 * warp + (lane & 15);
    const uint32_t selA = ((uint32_t)lane >> 4) << 4;
    const uint32_t aBase = smb + S_A + rowA * 128;
    const uint32_t mA = (rowA & 7) << 4;
    const int rowB = (lane & 7) + ((lane & 16) >> 1);
    const uint32_t selB = ((uint32_t)lane & 8) << 1;
    const uint32_t bBase = smb + wOff + rowB * 128;
    const uint32_t mB = (rowB & 7) << 4;
#pragma unroll
    for (int kt = 0; kt < 4; kt++) {
        uint32_t aAddr = aBase + ((32u * kt + selA) ^ mA);
        uint32_t a0[4], a1[4];
        LDSM4(a0, aAddr);
        LDSM4(a1, aAddr + 2048);
        uint32_t bx = (32u * kt + selB) ^ mB;
#pragma unroll
        for (int np = 0; np < 4; np++) {
            uint32_t bAddr = bBase + np * 2048 + bx;
            uint32_t bh[4], bl[4];
            LDSM4(bh, bAddr);
            LDSM4(bl, bAddr + 8192);
            MMA16(acc[0][2 * np], a0, bh[0], bh[1]);
            MMA16(acc[0][2 * np], a0, bl[0], bl[1]);
            MMA16(acc[0][2 * np + 1], a0, bh[2], bh[3]);
            MMA16(acc[0][2 * np + 1], a0, bl[2], bl[3]);
            MMA16(acc[1][2 * np], a1, bh[0], bh[1]);
            MMA16(acc[1][2 * np], a1, bl[0], bl[1]);
            MMA16(acc[1][2 * np + 1], a1, bh[2], bh[3]);
            MMA16(acc[1][2 * np + 1], a1, bl[2], bl[3]);
        }
    }
}

// GEMM with A fragments in registers (fp16), 2-pass B
__device__ __forceinline__ void gemm_regA(uint32_t smb, uint32_t wOff, int lane,
                                          const uint32_t mf[2][16],
                                          float acc[2][8][4]) {
    const int rowB = (lane & 7) + ((lane & 16) >> 1);
    const uint32_t selB = ((uint32_t)lane & 8) << 1;
    const uint32_t bBase = smb + wOff + rowB * 128;
    const uint32_t mB = (rowB & 7) << 4;
#pragma unroll
    for (int kt = 0; kt < 4; kt++) {
        uint32_t bx = (32u * kt + selB) ^ mB;
        const uint32_t* f0 = &mf[0][4 * kt];
        const uint32_t* f1 = &mf[1][4 * kt];
#pragma unroll
        for (int np = 0; np < 4; np++) {
            uint32_t bAddr = bBase + np * 2048 + bx;
            uint32_t bh[4], bl[4];
            LDSM4(bh, bAddr);
            LDSM4(bl, bAddr + 8192);
            MMA16(acc[0][2 * np], f0, bh[0], bh[1]);
            MMA16(acc[0][2 * np], f0, bl[0], bl[1]);
            MMA16(acc[0][2 * np + 1], f0, bh[2], bh[3]);
            MMA16(acc[0][2 * np + 1], f0, bl[2], bl[3]);
            MMA16(acc[1][2 * np], f1, bh[0], bh[1]);
            MMA16(acc[1][2 * np], f1, bl[0], bl[1]);
            MMA16(acc[1][2 * np + 1], f1, bh[2], bh[3]);
            MMA16(acc[1][2 * np + 1], f1, bl[2], bl[3]);
        }
    }
}

// ---------------- init (+ fused weight pre-split blocks) ----------------
__global__ void k_init(const float* __restrict__ feat,
                       const float* __restrict__ w_emb,
                       const float* __restrict__ b_emb,
                       const float* __restrict__ pos,
                       const float* __restrict__ we1,
                       const float* __restrict__ be1,
                       const float* __restrict__ we2,
                       const float* __restrict__ wx1) {
    int tid = threadIdx.x;
    if (blockIdx.x >= NT / 4) {
        if (tid >= 128) return;
        int layer = blockIdx.x - NT / 4;
        int n = tid & 63, kh = tid >> 6;
#pragma unroll
        for (int mIdx = 0; mIdx < 2; mIdx++) {
            const float* wsrc = (mIdx == 0 ? we2 : wx1) + layer * HD * HD;
            float wv[32];
#pragma unroll 8
            for (int kk = 0; kk < 32; kk++) wv[kk] = wsrc[(32 * kh + kk) * 64 + n];
#pragma unroll
            for (int jj = 0; jj < 4; jj++) {
                uint32_t hp[4], lp[4];
#pragma unroll
                for (int q = 0; q < 4; q++) {
                    float t0 = wv[8 * jj + 2 * q], t1 = wv[8 * jj + 2 * q + 1];
                    __half2 H = __floats2half2_rn(t0, t1);
                    hp[q] = *reinterpret_cast<uint32_t*>(&H);
                    float r0 = t0 - __low2float(H);
                    float r1 = t1 - __high2float(H);
                    lp[q] = packh2(r0, r1);
                }
                uint32_t sw = sw128((uint32_t)(n * 128 + kh * 64 + jj * 16)) >> 4;
                g_wpack[layer][2 * mIdx][sw]     = make_uint4(hp[0], hp[1], hp[2], hp[3]);
                g_wpack[layer][2 * mIdx + 1][sw] = make_uint4(lp[0], lp[1], lp[2], lp[3]);
            }
        }
        return;
    }
    extern __shared__ float smw[];
    __shared__ float fs[4][FD], hs[4][HD], Ax[4][HD], Bx[4][HD];
    int g = tid >> 6, j = tid & 63;
    int t = blockIdx.x * 4 + g;
    {
        float4* d = (float4*)smw;
        const float4* s1 = (const float4*)w_emb;
#pragma unroll
        for (int i = 0; i < 2; i++) d[tid + 256 * i] = __ldg(&s1[tid + 256 * i]);
        const float4* s2 = (const float4*)we1;
#pragma unroll
        for (int i = 0; i < 8; i++) d[512 + tid + 256 * i] = __ldg(&s2[tid + 256 * i]);
    }
    if (j < FD) fs[g][j] = feat[t * FD + j];
    __syncthreads();
    float acc = b_emb[j];
#pragma unroll
    for (int i = 0; i < FD; i++) acc += fs[g][i] * smw[i * HD + j];
    g_h[t * HD + j] = acc;
    hs[g][j] = acc;
    if (j < 8) g_x8[t * 8 + j] = (j < 6) ? pos[t * 3 + (j % 3)] : 0.0f;
    __syncthreads();
    {
        const float* w = smw + 2048;
        float a = 0, b = be1[j];
#pragma unroll 8
        for (int i = 0; i < HD; i++) {
            float hv = hs[g][i];
            a += hv * w[i * HD + j];
            b += hv * w[(64 + i) * HD + j];
        }
        Ax[g][j] = a; Bx[g][j] = b;
    }
    __syncthreads();
    if (j < 32) {
        g_Ah[t * 32 + j] = packh2(Ax[g][j], Ax[g][j + 32]);
        g_B2[t * 32 + j] = make_float2(Bx[g][j], Bx[g][j + 32]);
    }
}

// ---------------- edge kernel: TWO blocks (halves) per receiver -----------
__global__ void __launch_bounds__(128, 4)
k_edge_mma(const float* __restrict__ we1, const float* __restrict__ be2,
           const float* __restrict__ bx1, const float* __restrict__ wx2,
           int layer) {
    const float* we1l = we1 + layer * 130 * HD;
    const float* wx2l = wx2 + layer * HD * 2;
    const float* be2l = be2 + layer * HD;
    const float* bx1l = bx1 + layer * HD;

    extern __shared__ char sm[];
    char* aux = sm + S_AUX;
    float4* swq  = (float4*)(aux + AX_WQ);
    float2* sbr  = (float2*)(aux + AX_BR);
    float*  sbe2 = (float*)(aux + AX_BE2);
    float*  sbx1 = (float*)(aux + AX_BX1);
    float2* swx2 = (float2*)(aux + AX_WX2);
    float*  wpart = (float*)(aux + AX_WPART);
    float*  sphi = (float*)(aux + AX_SPHI);
    float*  sxu  = (float*)(aux + AX_SXU);

    const int r  = blockIdx.x >> 1;
    const int hf = blockIdx.x & 1;
    const int tid = threadIdx.x;
    const int warp = tid >> 5, lane = tid & 31;
    const int tig = lane & 3, gid = lane >> 2;
    const uint32_t smb = smem_u32(sm);

    {
        const uint4* wp = &g_wpack[layer][0][0];
        uint4* dst = (uint4*)(sm + S_W2H);
#pragma unroll
        for (int i = 0; i < 16; i++)
            dst[tid + 128 * i] = __ldg(&wp[tid + 128 * i]);
    }
    if (tid < 32) {
        swq[tid] = make_float4(we1l[8192 + tid], we1l[8256 + tid],
                               we1l[8192 + 32 + tid], we1l[8256 + 32 + tid]);
        sbr[tid] = g_B2[r * 32 + tid];
    }
    if (tid < 64) {
        sbe2[tid] = be2l[tid];
        sbx1[tid] = bx1l[tid];
        swx2[tid] = make_float2(wx2l[2 * tid], wx2l[2 * tid + 1]);
    }
    if (tid < 6) sxu[tid] = 0.0f;
    __syncthreads();

    const float4 xra = *(const float4*)&g_x8[r * 8];
    const float4 xrb = *(const float4*)&g_x8[r * 8 + 4];

    float aggv[16];
#pragma unroll
    for (int i = 0; i < 16; i++) aggv[i] = 0.0f;
    float xacc[6] = {0, 0, 0, 0, 0, 0};

    for (int tile = 3 * hf; tile < 3 * hf + 3; tile++) {
        const int s0 = tile * 128;
        const int s = s0 + tid;

        float4 xa = __ldg((const float4*)&g_x8[s * 8]);
        float4 xb = __ldg((const float4*)&g_x8[s * 8 + 4]);
        float d0 = xa.x - xra.x, d1 = xa.y - xra.y, d2 = xa.z - xra.z;
        float d3 = xa.w - xra.w, d4 = xb.x - xrb.x, d5 = xb.y - xrb.y;
        float sq0 = d0 * d0 + d1 * d1 + d2 * d2;
        float sq1 = d3 * d3 + d4 * d4 + d5 * d5;
        float r0 = __fdividef(1.0f, __fsqrt_rn(sq0 + 1e-8f) + 1.0f);
        float r1 = __fdividef(1.0f, __fsqrt_rn(sq1 + 1e-8f) + 1.0f);
        float sd0 = d0 * r0, sd1 = d1 * r0, sd2 = d2 * r0;
        float sd3 = d3 * r1, sd4 = d4 * r1, sd5 = d5 * r1;

        // ---- t-fill: A in fp16 (half the LDG traffic) ----
        {
            float tv[64];
            const uint4* arow = (const uint4*)&g_Ah[s * 32];
#pragma unroll
            for (int i4 = 0; i4 < 8; i4++) {
                uint4 a4 = __ldg(&arow[i4]);
                uint32_t aw[4] = {a4.x, a4.y, a4.z, a4.w};
#pragma unroll
                for (int q = 0; q < 4; q++) {
                    int c = 4 * i4 + q;
                    __half2 hv = *reinterpret_cast<__half2*>(&aw[q]);
                    float alo = __low2float(hv);
                    float ahi = __high2float(hv);
                    float4 wq = swq[c]; float2 br = sbr[c];
                    tv[c]      = silu(alo + br.x + sq0 * wq.x + sq1 * wq.y);
                    tv[c + 32] = silu(ahi + br.y + sq0 * wq.z + sq1 * wq.w);
                }
            }
#pragma unroll
            for (int j = 0; j < 8; j++) {
                uint32_t hp[4];
#pragma unroll
                for (int q = 0; q < 4; q++)
                    hp[q] = packh2(tv[8 * j + 2 * q], tv[8 * j + 2 * q + 1]);
                uint32_t sw = sw128((uint32_t)(tid * 128 + j * 16));
                *(uint4*)(sm + S_A + sw) = make_uint4(hp[0], hp[1], hp[2], hp[3]);
            }
        }
        __syncwarp();

        float acc[2][8][4];
        {
            int n0 = 2 * tig;
#pragma unroll
            for (int nt = 0; nt < 8; nt++) {
                float2 b = *(const float2*)&sbe2[8 * nt + n0];
                acc[0][nt][0] = b.x; acc[0][nt][1] = b.y;
                acc[0][nt][2] = b.x; acc[0][nt][3] = b.y;
                acc[1][nt][0] = b.x; acc[1][nt][1] = b.y;
                acc[1][nt][2] = b.x; acc[1][nt][3] = b.y;
            }
        }
        gemm_smemA(smb, S_W2H, warp, lane, acc);

        uint32_t mf[2][16];
#pragma unroll
        for (int mt = 0; mt < 2; mt++) {
            int rA = 32 * warp + 16 * mt + gid;
            float vA = (s0 + rA != r) ? 1.0f : 0.0f;
            float vB = (s0 + rA + 8 != r) ? 1.0f : 0.0f;
#pragma unroll
            for (int nt = 0; nt < 8; nt++) {
                float m0 = silu(acc[mt][nt][0]) * vA;
                float m1 = silu(acc[mt][nt][1]) * vA;
                float m2 = silu(acc[mt][nt][2]) * vB;
                float m3 = silu(acc[mt][nt][3]) * vB;
                aggv[2 * nt]     += m0 + m2;
                aggv[2 * nt + 1] += m1 + m3;
                mf[mt][2 * nt]     = packh2(m0, m1);
                mf[mt][2 * nt + 1] = packh2(m2, m3);
            }
        }

        {
            int n0 = 2 * tig;
#pragma unroll
            for (int nt = 0; nt < 8; nt++) {
                float2 b = *(const float2*)&sbx1[8 * nt + n0];
                acc[0][nt][0] = b.x; acc[0][nt][1] = b.y;
                acc[0][nt][2] = b.x; acc[0][nt][3] = b.y;
                acc[1][nt][0] = b.x; acc[1][nt][1] = b.y;
                acc[1][nt][2] = b.x; acc[1][nt][3] = b.y;
            }
        }
        gemm_regA(smb, S_WXH, lane, mf, acc);

        {
            float ph[4][2] = {{0, 0}, {0, 0}, {0, 0}, {0, 0}};
#pragma unroll
            for (int mt = 0; mt < 2; mt++) {
#pragma unroll
                for (int nt = 0; nt < 8; nt++) {
                    int n0 = 8 * nt + 2 * tig;
                    float4 w = *(const float4*)&swx2[n0];
                    float q0 = silu(acc[mt][nt][0]);
                    float q1 = silu(acc[mt][nt][1]);
                    float q2 = silu(acc[mt][nt][2]);
                    float q3 = silu(acc[mt][nt][3]);
                    ph[2 * mt][0]     += q0 * w.x + q1 * w.z;
                    ph[2 * mt][1]     += q0 * w.y + q1 * w.w;
                    ph[2 * mt + 1][0] += q2 * w.x + q3 * w.z;
                    ph[2 * mt + 1][1] += q2 * w.y + q3 * w.w;
                }
            }
#pragma unroll
            for (int k = 0; k < 4; k++) {
#pragma unroll
                for (int c = 0; c < 2; c++) {
                    ph[k][c] += __shfl_xor_sync(0xffffffffu, ph[k][c], 1);
                    ph[k][c] += __shfl_xor_sync(0xffffffffu, ph[k][c], 2);
                }
            }
            if (tig == 0) {
#pragma unroll
                for (int k = 0; k < 4; k++) {
                    int row = 32 * warp + 16 * (k >> 1) + 8 * (k & 1) + gid;
                    sphi[row * 2] = ph[k][0];
                    sphi[row * 2 + 1] = ph[k][1];
                }
            }
        }
        __syncwarp();
        {
            float2 p = *(const float2*)&sphi[tid * 2];
            xacc[0] += p.x * sd0; xacc[1] += p.x * sd1; xacc[2] += p.x * sd2;
            xacc[3] += p.y * sd3; xacc[4] += p.y * sd4; xacc[5] += p.y * sd5;
        }
        __syncwarp();
    }

    // ---- reductions (partial per half) ----
#pragma unroll
    for (int i = 0; i < 16; i++) {
        aggv[i] += __shfl_xor_sync(0xffffffffu, aggv[i], 4);
        aggv[i] += __shfl_xor_sync(0xffffffffu, aggv[i], 8);
        aggv[i] += __shfl_xor_sync(0xffffffffu, aggv[i], 16);
    }
    if (lane < 4) {
#pragma unroll
        for (int nt = 0; nt < 8; nt++) {
            wpart[warp * 64 + 8 * nt + 2 * lane]     = aggv[2 * nt];
            wpart[warp * 64 + 8 * nt + 2 * lane + 1] = aggv[2 * nt + 1];
        }
    }
#pragma unroll
    for (int c = 0; c < 6; c++) {
        float v = xacc[c];
#pragma unroll
        for (int off = 16; off > 0; off >>= 1)
            v += __shfl_xor_sync(0xffffffffu, v, off);
        if (lane == 0) atomicAdd(&sxu[c], v);
    }
    __syncthreads();
    if (tid < 64)
        g_aggP[hf][r * HD + tid] = wpart[tid] + wpart[64 + tid] +
                                   wpart[128 + tid] + wpart[192 + tid];
    if (tid < 6) g_xupdP[hf][r * 6 + tid] = sxu[tid];
}

// ---------------- node update layer 0 (8 nodes/block, 512 thr) ------------
__global__ void k_update(const float* __restrict__ wh1,
                         const float* __restrict__ bh1,
                         const float* __restrict__ wh2,
                         const float* __restrict__ bh2,
                         const float* __restrict__ we1,
                         const float* __restrict__ be1) {
    extern __shared__ float smw[];
    __shared__ float hs[8][HD], as[8][HD], us[8][HD], Ax[8][HD], Bx[8][HD];
    int tid = threadIdx.x;
    int g = tid >> 6, j = tid & 63;
    int t = blockIdx.x * 8 + g;
    {
        float4* d = (float4*)smw;
        const float4* s1 = (const float4*)wh1;
#pragma unroll
        for (int i = 0; i < 4; i++) d[tid + 512 * i] = __ldg(&s1[tid + 512 * i]);
        const float4* s2 = (const float4*)wh2;
#pragma unroll
        for (int i = 0; i < 2; i++) d[2048 + tid + 512 * i] = __ldg(&s2[tid + 512 * i]);
        const float4* s3 = (const float4*)(we1 + 130 * HD);
#pragma unroll
        for (int i = 0; i < 4; i++) d[3072 + tid + 512 * i] = __ldg(&s3[tid + 512 * i]);
    }
    hs[g][j] = g_h[t * HD + j];
    as[g][j] = g_aggP[0][t * HD + j] + g_aggP[1][t * HD + j];
    __syncthreads();
    float u = bh1[j];
#pragma unroll 8
    for (int i = 0; i < HD; i++) u += hs[g][i] * smw[i * HD + j];
#pragma unroll 8
    for (int i = 0; i < HD; i++) u += as[g][i] * smw[(64 + i) * HD + j];
    us[g][j] = silu(u);
    __syncthreads();
    float o = bh2[j];
#pragma unroll 8
    for (int i = 0; i < HD; i++) o += us[g][i] * smw[8192 + i * HD + j];
    float hn = hs[g][j] + o;
    g_h[t * HD + j] = hn;
    if (j < 6)
        g_x8[t * 8 + j] += (g_xupdP[0][t * 6 + j] + g_xupdP[1][t * 6 + j]) * INV_T1;
    hs[g][j] = hn;
    __syncthreads();
    {
        const float* w = smw + 12288;
        float a = 0, b = be1[HD + j];
#pragma unroll 8
        for (int i = 0; i < HD; i++) {
            float hv = hs[g][i];
            a += hv * w[i * HD + j];
            b += hv * w[(64 + i) * HD + j];
        }
        Ax[g][j] = a; Bx[g][j] = b;
    }
    __syncthreads();
    if (j < 32) {
        g_Ah[t * 32 + j] = packh2(Ax[g][j], Ax[g][j + 32]);
        g_B2[t * 32 + j] = make_float2(Bx[g][j], Bx[g][j + 32]);
    }
}

// ---------------- node update layer 1 + final head (merged) ---------------
__global__ void k_updfin(const float* __restrict__ wh1,
                         const float* __restrict__ bh1,
                         const float* __restrict__ wh2,
                         const float* __restrict__ bh2,
                         const float* __restrict__ pos,
                         const float* __restrict__ w_head,
                         const float* __restrict__ b_head,
                         float* __restrict__ out) {
    extern __shared__ float smw[];
    __shared__ float hs[8][HD], as[8][HD], us[8][HD];
    int tid = threadIdx.x;
    int g = tid >> 6, j = tid & 63;
    int t = blockIdx.x * 8 + g;
    {
        float4* d = (float4*)smw;
        const float4* s1 = (const float4*)(wh1 + 128 * HD);
#pragma unroll
        for (int i = 0; i < 4; i++) d[tid + 512 * i] = __ldg(&s1[tid + 512 * i]);
        const float4* s2 = (const float4*)(wh2 + HD * HD);
#pragma unroll
        for (int i = 0; i < 2; i++) d[2048 + tid + 512 * i] = __ldg(&s2[tid + 512 * i]);
        const float4* s3 = (const float4*)w_head;
#pragma unroll
        for (int i = 0; i < 2; i++) d[3072 + tid + 512 * i] = __ldg(&s3[tid + 512 * i]);
    }
    hs[g][j] = g_h[t * HD + j];
    as[g][j] = g_aggP[0][t * HD + j] + g_aggP[1][t * HD + j];
    __syncthreads();
    float u = bh1[HD + j];
#pragma unroll 8
    for (int i = 0; i < HD; i++) u += hs[g][i] * smw[i * HD + j];
#pragma unroll 8
    for (int i = 0; i < HD; i++) u += as[g][i] * smw[(64 + i) * HD + j];
    us[g][j] = silu(u);
    __syncthreads();
    float o = bh2[HD + j];
#pragma unroll 8
    for (int i = 0; i < HD; i++) o += us[g][i] * smw[8192 + i * HD + j];
    float hn = hs[g][j] + o;
    if (j < 6) {
        float xv = g_x8[t * 8 + j] +
                   (g_xupdP[0][t * 6 + j] + g_xupdP[1][t * 6 + j]) * INV_T1;
        out[t * 6 + j] = xv - pos[t * 3 + (j % 3)];
    }
    hs[g][j] = hn;
    __syncthreads();
    float oh = b_head[j];
#pragma unroll 8
    for (int i = 0; i < HD; i++) oh += hs[g][i] * smw[12288 + i * OUTD + j];
    out[VEC_OUT + t * OUTD + j] = oh;
}

// ---------------- launch ----------------
extern "C" void kernel_launch(void* const* d_in, const int* in_sizes, int n_in,
                              void* d_out, int out_size) {
    const float* positions = (const float*)d_in[0];
    const float* features  = (const float*)d_in[1];
    const float* w_emb     = (const float*)d_in[2];
    const float* b_emb     = (const float*)d_in[3];
    const float* we1       = (const float*)d_in[4];
    const float* be1       = (const float*)d_in[5];
    const float* we2       = (const float*)d_in[6];
    const float* be2       = (const float*)d_in[7];
    const float* wx1       = (const float*)d_in[8];
    const float* bx1       = (const float*)d_in[9];
    const float* wx2       = (const float*)d_in[10];
    const float* wh1       = (const float*)d_in[11];
    const float* bh1       = (const float*)d_in[12];
    const float* wh2       = (const float*)d_in[13];
    const float* bh2       = (const float*)d_in[14];
    const float* w_head    = (const float*)d_in[15];
    const float* b_head    = (const float*)d_in[16];
    float* out = (float*)d_out;

    cudaFuncSetAttribute(k_edge_mma, cudaFuncAttributeMaxDynamicSharedMemorySize,
                         EDGE_SMEM);
    cudaFuncSetAttribute(k_update, cudaFuncAttributeMaxDynamicSharedMemorySize,
                         UPD_SMEM);
    cudaFuncSetAttribute(k_updfin, cudaFuncAttributeMaxDynamicSharedMemorySize,
                         UPDFIN_SMEM);
    cudaFuncSetAttribute(k_init, cudaFuncAttributeMaxDynamicSharedMemorySize,
                         INIT_SMEM);

    k_init<<<NT / 4 + LL, 256, INIT_SMEM>>>(features, w_emb, b_emb, positions,
                                            we1, be1, we2, wx1);
    k_edge_mma<<<2 * NT, 128, EDGE_SMEM>>>(we1, be2, bx1, wx2, 0);
    k_update<<<NT / 8, 512, UPD_SMEM>>>(wh1, bh1, wh2, bh2, we1, be1);
    k_edge_mma<<<2 * NT, 128, EDGE_SMEM>>>(we1, be2, bx1, wx2, 1);
    k_updfin<<<NT / 8, 512, UPDFIN_SMEM>>>(wh1, bh1, wh2, bh2, positions,
                                           w_head, b_head, out);
}